// round 13
// baseline (speedup 1.0000x reference)
#include <cuda_runtime.h>
#include <cuda_fp16.h>
#include <math.h>
#include <stdint.h>

#define NN   300000
#define NE   299999
#define NA   150000
#define DD   64
#define HH   128

// ---------------- scratch ----------------
__device__ float  g_h   [(size_t)NN * HH];
__device__ __half g_xl  [(size_t)NN * HH];
__device__ __half g_xr  [(size_t)NN * HH];
__device__ __half g_acc [(size_t)NN * HH];
__device__ float  g_den [NN];
__device__ float  g_cadd[HH];

// ---------------- fp16 mma helper ----------------
__device__ __forceinline__ void mma_f16(float* d, const uint32_t* a, const uint32_t* b)
{
    asm volatile(
        "mma.sync.aligned.m16n8k16.row.col.f32.f16.f16.f32 "
        "{%0,%1,%2,%3},{%4,%5,%6,%7},{%8,%9},{%0,%1,%2,%3};"
        : "+f"(d[0]), "+f"(d[1]), "+f"(d[2]), "+f"(d[3])
        : "r"(a[0]), "r"(a[1]), "r"(a[2]), "r"(a[3]), "r"(b[0]), "r"(b[1]));
}

#define KBP  72      // W smem pitch [n][k] in halves (36 words ≡ 4 mod 32: conflict-free)
#define APD  136     // A pitch (K=128) halves (68 ≡ 4 mod 32)
#define APE  72      // A pitch (K=64)  halves (36 ≡ 4 mod 32)
#define APHD 264     // A pitch (K=256, head) halves (132 ≡ 4 mod 32)

// fp16 mainloop over one 64-k chunk (4 mma k-steps). Warp tile (MF*16) x (NF*8).
// A: row-major halves pitch KPh (+ a_off halves). W: [n][k] halves pitch KBP (local k).
template <int MF, int NF>
__device__ __forceinline__ void mma_chunk64h(
    const __half* AsH, int KPh, int a_off, const __half* WsH,
    int wrow, int wcol, int gid, int tig, float acc[MF][NF][4])
{
#pragma unroll
    for (int ks = 0; ks < 4; ++ks) {
        const int k0 = ks * 16;
        uint32_t a[MF][4], b[NF][2];
#pragma unroll
        for (int mf = 0; mf < MF; ++mf) {
            const __half* ap = AsH + (wrow + mf * 16 + gid) * KPh + a_off + k0 + 2 * tig;
            a[mf][0] = *(const uint32_t*)(ap);
            a[mf][1] = *(const uint32_t*)(ap + 8 * KPh);
            a[mf][2] = *(const uint32_t*)(ap + 8);
            a[mf][3] = *(const uint32_t*)(ap + 8 * KPh + 8);
        }
#pragma unroll
        for (int nf = 0; nf < NF; ++nf) {
            const __half* bp = WsH + (wcol + nf * 8 + gid) * KBP + k0 + 2 * tig;
            b[nf][0] = *(const uint32_t*)(bp);
            b[nf][1] = *(const uint32_t*)(bp + 8);
        }
#pragma unroll
        for (int mf = 0; mf < MF; ++mf)
#pragma unroll
            for (int nf = 0; nf < NF; ++nf)
                mma_f16(acc[mf][nf], a[mf], b[nf]);
    }
}

// stage one 64-k W chunk [64 x 128] row-major fp32 -> WsH [n][k] fp16 (transposed)
__device__ __forceinline__ void stage_wT(const float* __restrict__ W, __half* WsH, int tid)
{
    int n = tid & 127;
    for (int k = (tid >> 7) * 2; k < 64; k += 4) {
        float w0 = W[(size_t)k * 128 + n];
        float w1 = W[(size_t)(k + 1) * 128 + n];
        *(__half2*)(WsH + n * KBP + k) = __floats2half2_rn(w0, w1);
    }
}

#define ZACC(acc, MF, NF)                             \
    _Pragma("unroll") for (int mf = 0; mf < MF; ++mf) \
    _Pragma("unroll") for (int nf = 0; nf < NF; ++nf) \
    _Pragma("unroll") for (int j = 0; j < 4; ++j) acc[mf][nf][j] = 0.f;

// epilogue: write acc(+bias) to C as fp16
__device__ __forceinline__ void write_c_h(
    __half* __restrict__ C, const float* __restrict__ bias,
    int row0, int wrow, int wcol, int gid, int tig,
    float acc[2][4][4], int M)
{
#pragma unroll
    for (int nf = 0; nf < 4; ++nf) {
        const int c = wcol + nf * 8 + tig * 2;
        const float b0 = bias[c], b1 = bias[c + 1];
#pragma unroll
        for (int mf = 0; mf < 2; ++mf)
#pragma unroll
            for (int h = 0; h < 2; ++h) {
                const int r = row0 + wrow + mf * 16 + h * 8 + gid;
                if (r < M)
                    *(__half2*)(C + (size_t)r * 128 + c) =
                        __floats2half2_rn(acc[mf][nf][2 * h] + b0, acc[mf][nf][2 * h + 1] + b1);
            }
    }
}

// ---------- fused embed + dual transform (BM=64, 3 CTAs/SM) + acc/den zeroing ----------
__global__ __launch_bounds__(256, 3) void embed_dual(
    const float* __restrict__ x,
    const float* __restrict__ We, const float* __restrict__ be,
    const float* __restrict__ Wl, const float* __restrict__ bl,
    const float* __restrict__ Wr, const float* __restrict__ br,
    float* __restrict__ Hout, __half* __restrict__ Cl, __half* __restrict__ Cr,
    __half* __restrict__ Accz, float* __restrict__ Denz, int M)
{
    extern __shared__ __half shh[];
    __half* AsH = shh;                 // 64 x APD (phase A uses pitch APE)
    __half* WsH = shh + 64 * APD;      // 128 x KBP
    const int tid = threadIdx.x;
    const int row0 = blockIdx.x * 64;

    // zero this block's slice of acc (fp16) and den
    {
        const uint4 z = make_uint4(0u, 0u, 0u, 0u);
        int nrow = min(64, M - row0);
        for (int i = tid; i < nrow * 16; i += 256)
            ((uint4*)Accz)[(size_t)row0 * 16 + i] = z;
        if (tid < nrow) Denz[row0 + tid] = 0.f;
    }

    // phase A: stage We^T + x (fp16, pitch APE)
    stage_wT(We, WsH, tid);
    for (int i = tid; i < 64 * 16; i += 256) {
        int r = i >> 4, c4 = i & 15;
        int gr = row0 + r;
        float4 v = make_float4(0.f, 0.f, 0.f, 0.f);
        if (gr < M) v = ((const float4*)(x + (size_t)gr * 64))[c4];
        __half2* ap = (__half2*)(AsH + r * APE + c4 * 4);
        ap[0] = __floats2half2_rn(v.x, v.y);
        ap[1] = __floats2half2_rn(v.z, v.w);
    }
    __syncthreads();

    const int wid = tid >> 5, lane = tid & 31;
    const int wm = wid & 1, wn = wid >> 1;          // 2x4 warp grid, tile 32x32
    const int wrow = wm * 32, wcol = wn * 32;
    const int gid = lane >> 2, tig = lane & 3;

    float acc[2][4][4];
    ZACC(acc, 2, 4)
    mma_chunk64h<2, 4>(AsH, APE, 0, WsH, wrow, wcol, gid, tig, acc);
    __syncthreads();   // phase-A reads complete before AsH/WsH overwrite

    // epilogue h: write gmem fp32 + restage fp16 into AsH (pitch APD)
#pragma unroll
    for (int nf = 0; nf < 4; ++nf) {
        const int c = wcol + nf * 8 + tig * 2;
        const float b0 = be[c], b1 = be[c + 1];
#pragma unroll
        for (int mf = 0; mf < 2; ++mf)
#pragma unroll
            for (int h = 0; h < 2; ++h) {
                const int rl = wrow + mf * 16 + h * 8 + gid;
                const float v0 = acc[mf][nf][2 * h] + b0;
                const float v1 = acc[mf][nf][2 * h + 1] + b1;
                const int gr = row0 + rl;
                if (gr < M)
                    *(float2*)(Hout + (size_t)gr * 128 + c) = make_float2(v0, v1);
                *(__half2*)(AsH + rl * APD + c) = __floats2half2_rn(v0, v1);
            }
    }

#pragma unroll
    for (int ph = 0; ph < 2; ++ph) {
        const float* W    = ph ? Wr : Wl;
        const float* bias = ph ? br : bl;
        __half* C         = ph ? Cr : Cl;
        ZACC(acc, 2, 4)
#pragma unroll
        for (int kc = 0; kc < 2; ++kc) {
            __syncthreads();
            stage_wT(W + (size_t)kc * 64 * 128, WsH, tid);
            __syncthreads();
            mma_chunk64h<2, 4>(AsH, APD, kc * 64, WsH, wrow, wcol, gid, tig, acc);
        }
        write_c_h(C, bias, row0, wrow, wcol, gid, tig, acc, M);
    }
}

// ---------- dual transform with fused update + zero-after-read (BM=64, 3 CTAs/SM) ----------
__global__ __launch_bounds__(256, 3) void dual_upd(
    float* __restrict__ H, __half* __restrict__ Acc, float* __restrict__ Den,
    const float* __restrict__ ubias,
    const float* __restrict__ Wl, const float* __restrict__ bl,
    const float* __restrict__ Wr, const float* __restrict__ br,
    __half* __restrict__ Cl, __half* __restrict__ Cr, int M)
{
    extern __shared__ __half shh[];
    __half* AsH = shh;                 // 64 x APD
    __half* WsH = shh + 64 * APD;      // 128 x KBP
    const int tid = threadIdx.x;
    const int row0 = blockIdx.x * 64;

    // stage A with fused update: h1 = h + relu(acc/den + ubias)
    for (int i = tid; i < 64 * 32; i += 256) {
        int r = i >> 5, c4 = i & 31;
        int gr = row0 + r;
        float4 hv = make_float4(0.f, 0.f, 0.f, 0.f);
        if (gr < M) {
            float inv = 1.f / (Den[gr] + 1e-16f);
            const __half2* ah = (const __half2*)Acc + (size_t)gr * 64 + c4 * 2;
            float2 a01 = __half22float2(ah[0]);
            float2 a23 = __half22float2(ah[1]);
            hv = ((const float4*)H)[(size_t)gr * 32 + c4];
            const float4 bb = ((const float4*)ubias)[c4];
            hv.x += fmaxf(a01.x * inv + bb.x, 0.f);
            hv.y += fmaxf(a01.y * inv + bb.y, 0.f);
            hv.z += fmaxf(a23.x * inv + bb.z, 0.f);
            hv.w += fmaxf(a23.y * inv + bb.w, 0.f);
            ((float4*)H)[(size_t)gr * 32 + c4] = hv;
        }
        __half2* ap = (__half2*)(AsH + r * APD + c4 * 4);
        ap[0] = __floats2half2_rn(hv.x, hv.y);
        ap[1] = __floats2half2_rn(hv.z, hv.w);
    }
    __syncthreads();   // ALL acc/den reads for this block's rows complete

    // zero-after-read: re-zero acc/den for the next edge pass
    {
        const uint4 z = make_uint4(0u, 0u, 0u, 0u);
        int nrow = min(64, M - row0);
        for (int i = tid; i < nrow * 16; i += 256)
            ((uint4*)Acc)[(size_t)row0 * 16 + i] = z;
        if (tid < nrow) Den[row0 + tid] = 0.f;
    }

    const int wid = tid >> 5, lane = tid & 31;
    const int wm = wid & 1, wn = wid >> 1;
    const int wrow = wm * 32, wcol = wn * 32;
    const int gid = lane >> 2, tig = lane & 3;

    float acc[2][4][4];
#pragma unroll
    for (int ph = 0; ph < 2; ++ph) {
        const float* W    = ph ? Wr : Wl;
        const float* bias = ph ? br : bl;
        __half* C         = ph ? Cr : Cl;
        ZACC(acc, 2, 4)
#pragma unroll
        for (int kc = 0; kc < 2; ++kc) {
            __syncthreads();
            stage_wT(W + (size_t)kc * 64 * 128, WsH, tid);
            __syncthreads();
            mma_chunk64h<2, 4>(AsH, APD, kc * 64, WsH, wrow, wcol, gid, tig, acc);
        }
        write_c_h(C, bias, row0, wrow, wcol, gid, tig, acc, M);
    }
}

// ---------- fused edge pass: warp per edge, fp16 xl/xr/acc ----------
__global__ void edge_kernel(const int* __restrict__ src, const int* __restrict__ dst,
                            const float* __restrict__ att)
{
    int e = (int)(((size_t)blockIdx.x * blockDim.x + threadIdx.x) >> 5);
    if (e >= NE) return;
    int ln = threadIdx.x & 31;
    int s = src[e], d = dst[e];
    const __half2* xap = (const __half2*)g_xl + (size_t)s * 64 + ln * 2;
    const __half2* xbp = (const __half2*)g_xr + (size_t)d * 64 + ln * 2;
    __half2 xa2[2], xb2[2];
    *(uint2*)xa2 = *(const uint2*)xap;
    *(uint2*)xb2 = *(const uint2*)xbp;
    float2 xa01 = __half22float2(xa2[0]);
    float2 xa23 = __half22float2(xa2[1]);
    float2 xb01 = __half22float2(xb2[0]);
    float2 xb23 = __half22float2(xb2[1]);
    float4 at = ((const float4*)att)[ln];

    float vx = xa01.x + xb01.x; vx = vx > 0.f ? vx : 0.2f * vx;
    float vy = xa01.y + xb01.y; vy = vy > 0.f ? vy : 0.2f * vy;
    float vz = xa23.x + xb23.x; vz = vz > 0.f ? vz : 0.2f * vz;
    float vw = xa23.y + xb23.y; vw = vw > 0.f ? vw : 0.2f * vw;
    float p = vx * at.x + vy * at.y + vz * at.z + vw * at.w;
#pragma unroll
    for (int o = 16; o > 0; o >>= 1) p += __shfl_xor_sync(0xffffffffu, p, o);
    float e_ = __expf(p);
    if (ln == 0) atomicAdd(&g_den[d], e_);
    __half2* accd = (__half2*)g_acc + (size_t)d * 64 + ln * 2;
    atomicAdd(accd + 0, __floats2half2_rn(e_ * xa01.x, e_ * xa01.y));
    atomicAdd(accd + 1, __floats2half2_rn(e_ * xa23.x, e_ * xa23.y));
}

// ---------- mega head: BM=64, warp tile 32x32 grid 2x4, 2 CTAs/SM ----------
__global__ __launch_bounds__(256, 2) void head_kernel(
    const float* __restrict__ H, const __half* __restrict__ Acc, const float* __restrict__ Den,
    const float* __restrict__ ubias,
    const int* __restrict__ child, const int* __restrict__ parent,
    const float* __restrict__ ttab, const int* __restrict__ timei,
    const float* __restrict__ W_comb, const float* __restrict__ b_comb,
    const float* __restrict__ W_a1, const float* __restrict__ cadd,
    const float* __restrict__ W_a2, const float* __restrict__ b_a2,
    float* __restrict__ out, int M)
{
    extern __shared__ __half shh[];
    __half* AsH = shh;                       // 64 x APHD
    __half* WsH = shh + 64 * APHD;           // 128 x KBP
    float*  red = (float*)(WsH + 128 * KBP); // 4 x 64
    const int tid = threadIdx.x;
    const int row0 = blockIdx.x * 64;

    // stage cat(h2[child], h2[parent]|0), h2 = h1 + relu(acc/den + ubias)
    for (int i = tid; i < 64 * 64; i += 256) {
        int r = i >> 6, c4 = i & 63;
        int gr = row0 + r;
        float4 v = make_float4(0.f, 0.f, 0.f, 0.f);
        if (gr < M) {
            int cc = c4 < 32 ? c4 : c4 - 32;
            int ri = c4 < 32 ? child[gr] : parent[gr];
            if (ri >= 0) {
                float inv = 1.f / (Den[ri] + 1e-16f);
                const __half2* ah = (const __half2*)Acc + (size_t)ri * 64 + cc * 2;
                float2 a01 = __half22float2(ah[0]);
                float2 a23 = __half22float2(ah[1]);
                v = ((const float4*)H)[(size_t)ri * 32 + cc];
                float4 bb = ((const float4*)ubias)[cc];
                v.x += fmaxf(a01.x * inv + bb.x, 0.f);
                v.y += fmaxf(a01.y * inv + bb.y, 0.f);
                v.z += fmaxf(a23.x * inv + bb.z, 0.f);
                v.w += fmaxf(a23.y * inv + bb.w, 0.f);
            }
        }
        __half2* ap = (__half2*)(AsH + r * APHD + c4 * 4);
        ap[0] = __floats2half2_rn(v.x, v.y);
        ap[1] = __floats2half2_rn(v.z, v.w);
    }

    const int wid = tid >> 5, lane = tid & 31;
    const int wm = wid & 1, wn = wid >> 1;        // 2x4 warp grid, tile 32x32
    const int wrow = wm * 32, wcol = wn * 32;
    const int gid = lane >> 2, tig = lane & 3;

    float acc[2][4][4];
    ZACC(acc, 2, 4)

    // GEMM1: branch = cat @ W_comb  (K=256, 4 chunks)
#pragma unroll
    for (int kc = 0; kc < 4; ++kc) {
        __syncthreads();
        stage_wT(W_comb + (size_t)kc * 64 * 128, WsH, tid);
        __syncthreads();
        mma_chunk64h<2, 4>(AsH, APHD, kc * 64, WsH, wrow, wcol, gid, tig, acc);
    }
    __syncthreads();   // GEMM1 AsH reads complete before overwrite

    // epilogue1: branch(+b_comb) -> AsH cols [0,128)
#pragma unroll
    for (int nf = 0; nf < 4; ++nf) {
        const int c = wcol + nf * 8 + tig * 2;
        const float b0 = b_comb[c], b1 = b_comb[c + 1];
#pragma unroll
        for (int mf = 0; mf < 2; ++mf)
#pragma unroll
            for (int h = 0; h < 2; ++h) {
                const int rl = wrow + mf * 16 + h * 8 + gid;
                *(__half2*)(AsH + rl * APHD + c) =
                    __floats2half2_rn(acc[mf][nf][2 * h] + b0, acc[mf][nf][2 * h + 1] + b1);
            }
    }
    // stage t_emb -> AsH cols [128,256)
    for (int i = tid; i < 64 * 32; i += 256) {
        int r = i >> 5, c4 = i & 31;
        int gr = row0 + r;
        float4 v = make_float4(0.f, 0.f, 0.f, 0.f);
        if (gr < M) {
            int t = timei[gr];
            v = ((const float4*)(ttab + (size_t)t * 128))[c4];
        }
        __half2* ap = (__half2*)(AsH + r * APHD + 128 + c4 * 4);
        ap[0] = __floats2half2_rn(v.x, v.y);
        ap[1] = __floats2half2_rn(v.z, v.w);
    }

    // GEMM2: hidden = relu(cat @ W_a1 + cadd)
    ZACC(acc, 2, 4)
#pragma unroll
    for (int kc = 0; kc < 4; ++kc) {
        __syncthreads();
        stage_wT(W_a1 + (size_t)kc * 64 * 128, WsH, tid);
        __syncthreads();
        mma_chunk64h<2, 4>(AsH, APHD, kc * 64, WsH, wrow, wcol, gid, tig, acc);
    }

    // epilogue2: dot with W_a2
    float p[2][2] = {{0.f, 0.f}, {0.f, 0.f}};
#pragma unroll
    for (int nf = 0; nf < 4; ++nf) {
        const int c = wcol + nf * 8 + tig * 2;
        const float ca0 = cadd[c], ca1 = cadd[c + 1];
        const float w20 = W_a2[c], w21 = W_a2[c + 1];
#pragma unroll
        for (int mf = 0; mf < 2; ++mf)
#pragma unroll
            for (int h = 0; h < 2; ++h) {
                float v0 = fmaxf(acc[mf][nf][2 * h]     + ca0, 0.f);
                float v1 = fmaxf(acc[mf][nf][2 * h + 1] + ca1, 0.f);
                p[mf][h] += v0 * w20 + v1 * w21;
            }
    }
#pragma unroll
    for (int o = 1; o <= 2; o <<= 1)
#pragma unroll
        for (int mf = 0; mf < 2; ++mf)
#pragma unroll
            for (int h = 0; h < 2; ++h)
                p[mf][h] += __shfl_xor_sync(0xffffffffu, p[mf][h], o);

    __syncthreads();
    if (tig == 0) {
#pragma unroll
        for (int mf = 0; mf < 2; ++mf)
#pragma unroll
            for (int h = 0; h < 2; ++h)
                red[wn * 64 + wrow + mf * 16 + h * 8 + gid] = p[mf][h];
    }
    __syncthreads();
    if (tid < 64) {
        int gr = row0 + tid;
        if (gr < M)
            out[gr] = red[tid] + red[64 + tid] + red[128 + tid] + red[192 + tid] + b_a2[0];
    }
}

// ---------------- fused context precompute ----------------
__global__ void ctx_cadd_kernel(const float* __restrict__ focal, const float* __restrict__ W_seq,
                                const float* __restrict__ b_seq,
                                const float* __restrict__ W_a1, const float* __restrict__ b_a1)
{
    __shared__ float cs[128];
    int j = threadIdx.x;
    float s = b_seq[j];
    for (int d = 0; d < DD; ++d) s += focal[d] * W_seq[d * 128 + j];
    cs[j] = s;
    __syncthreads();
    float t = b_a1[j];
    for (int k = 0; k < 128; ++k) t += cs[k] * W_a1[(256 + k) * 128 + j];
    g_cadd[j] = t;
}

// ---------------- launch ----------------
extern "C" void kernel_launch(void* const* d_in, const int* in_sizes, int n_in,
                              void* d_out, int out_size)
{
    const float* x       = (const float*)d_in[0];
    const int*   ei      = (const int*)  d_in[1];
    const float* focal   = (const float*)d_in[2];
    const int*   child   = (const int*)  d_in[3];
    const int*   parent  = (const int*)  d_in[4];
    const int*   timei   = (const int*)  d_in[5];
    const float* W_embed = (const float*)d_in[6];
    const float* b_embed = (const float*)d_in[7];
    const float* bu_Wl   = (const float*)d_in[8];
    const float* bu_bl   = (const float*)d_in[9];
    const float* bu_Wr   = (const float*)d_in[10];
    const float* bu_br   = (const float*)d_in[11];
    const float* bu_att  = (const float*)d_in[12];
    const float* bu_bias = (const float*)d_in[13];
    const float* td_Wl   = (const float*)d_in[14];
    const float* td_bl   = (const float*)d_in[15];
    const float* td_Wr   = (const float*)d_in[16];
    const float* td_br   = (const float*)d_in[17];
    const float* td_att  = (const float*)d_in[18];
    const float* td_bias = (const float*)d_in[19];
    const float* ttab    = (const float*)d_in[20];
    const float* W_comb  = (const float*)d_in[21];
    const float* b_comb  = (const float*)d_in[22];
    const float* W_a1    = (const float*)d_in[23];
    const float* b_a1    = (const float*)d_in[24];
    const float* W_a2    = (const float*)d_in[25];
    const float* b_a2    = (const float*)d_in[26];
    const float* W_seq   = (const float*)d_in[27];
    const float* b_seq   = (const float*)d_in[28];
    float* out = (float*)d_out;

    const int SM_DUAL = (64 * APD + 128 * KBP) * 2;               // 35,840 B (3 CTAs/SM)
    const int SM_HEAD = (64 * APHD + 128 * KBP) * 2 + 256 * 4;    // 53,248 B (2 CTAs/SM)
    cudaFuncSetAttribute(embed_dual,  cudaFuncAttributeMaxDynamicSharedMemorySize, SM_DUAL);
    cudaFuncSetAttribute(dual_upd,    cudaFuncAttributeMaxDynamicSharedMemorySize, SM_DUAL);
    cudaFuncSetAttribute(head_kernel, cudaFuncAttributeMaxDynamicSharedMemorySize, SM_HEAD);

    float *hp, *denp, *caddp;
    __half *xlp, *xrp, *accp;
    cudaGetSymbolAddress((void**)&hp,    g_h);
    cudaGetSymbolAddress((void**)&xlp,   g_xl);
    cudaGetSymbolAddress((void**)&xrp,   g_xr);
    cudaGetSymbolAddress((void**)&accp,  g_acc);
    cudaGetSymbolAddress((void**)&denp,  g_den);
    cudaGetSymbolAddress((void**)&caddp, g_cadd);

    const int GEMM_BLKS_N = (NN + 63) / 64;
    const int HEAD_BLKS   = (NA + 63) / 64;
    const int EDGE_BLKS   = (NE + 7) / 8;

    // 0) context fold (tiny, no deps on pipeline)
    ctx_cadd_kernel<<<1, 128>>>(focal, W_seq, b_seq, W_a1, b_a1);

    // 1) embed + bottom-up transforms + acc/den zeroing (src = row1, dst = row0)
    embed_dual<<<GEMM_BLKS_N, 256, SM_DUAL>>>(x, W_embed, b_embed,
                                              bu_Wl, bu_bl, bu_Wr, bu_br,
                                              hp, xlp, xrp, accp, denp, NN);
    edge_kernel<<<EDGE_BLKS, 256>>>(ei + NE, ei, bu_att);

    // 2) update1 fused + top-down transforms + zero-after-read (src = row0, dst = row1)
    dual_upd<<<GEMM_BLKS_N, 256, SM_DUAL>>>(hp, accp, denp, bu_bias,
                                            td_Wl, td_bl, td_Wr, td_br,
                                            xlp, xrp, NN);
    edge_kernel<<<EDGE_BLKS, 256>>>(ei, ei + NE, td_att);

    // 3) head with on-the-fly update2
    head_kernel<<<HEAD_BLKS, 256, SM_HEAD>>>(hp, accp, denp, td_bias,
                                             child, parent, ttab, timei,
                                             W_comb, b_comb, W_a1, caddp,
                                             W_a2, b_a2, out, NA);
}

// round 14
// speedup vs baseline: 1.2846x; 1.2846x over previous
#include <cuda_runtime.h>
#include <cuda_fp16.h>
#include <math.h>
#include <stdint.h>

#define NN   300000
#define NE   299999
#define NA   150000
#define DD   64
#define HH   128

// ---------------- scratch ----------------
__device__ float  g_h   [(size_t)NN * HH];
__device__ __half g_xl  [(size_t)NN * HH];
__device__ __half g_xr  [(size_t)NN * HH];
__device__ __half g_acc [(size_t)NN * HH];
__device__ float  g_den [NN];
__device__ float  g_cadd[HH];

// ---------------- helpers ----------------
__device__ __forceinline__ uint32_t smem_u32(const void* p)
{
    uint32_t a;
    asm("{ .reg .u64 t; cvta.to.shared.u64 t, %1; cvt.u32.u64 %0, t; }" : "=r"(a) : "l"(p));
    return a;
}

__device__ __forceinline__ void mma_f16(float* d, const uint32_t* a, const uint32_t* b)
{
    asm volatile(
        "mma.sync.aligned.m16n8k16.row.col.f32.f16.f16.f32 "
        "{%0,%1,%2,%3},{%4,%5,%6,%7},{%8,%9},{%0,%1,%2,%3};"
        : "+f"(d[0]), "+f"(d[1]), "+f"(d[2]), "+f"(d[3])
        : "r"(a[0]), "r"(a[1]), "r"(a[2]), "r"(a[3]), "r"(b[0]), "r"(b[1]));
}

__device__ __forceinline__ void ldsm_x4(uint32_t* r, uint32_t addr)
{
    asm volatile("ldmatrix.sync.aligned.m8n8.x4.shared.b16 {%0,%1,%2,%3}, [%4];"
                 : "=r"(r[0]), "=r"(r[1]), "=r"(r[2]), "=r"(r[3]) : "r"(addr));
}
__device__ __forceinline__ void ldsm_x2t(uint32_t* r, uint32_t addr)
{
    asm volatile("ldmatrix.sync.aligned.m8n8.x2.trans.shared.b16 {%0,%1}, [%2];"
                 : "=r"(r[0]), "=r"(r[1]) : "r"(addr));
}

// pitches in halves; all give row pitch ≡ 4 words mod 32 -> ldmatrix conflict-free
#define WKN  136     // W smem [k][n] pitch (n=128+8)
#define APE  72      // A pitch (K=64)
#define APD  136     // A pitch (K=128)
#define APHD 264     // A pitch (K=256, head)

// fp16 mainloop over one 64-k chunk (4 mma k-steps). Warp tile (MF*16) x (NF*8).
// A: [m][k] halves pitch KPh (+ a_off halves). W: [k][n] halves pitch WKN (local k).
template <int MF, int NF>
__device__ __forceinline__ void mma_chunk64h(
    const __half* AsH, int KPh, int a_off, const __half* WsH,
    int wrow, int wcol, int lane, float acc[MF][NF][4])
{
    const int l15 = lane & 15, lg = lane >> 4;
#pragma unroll
    for (int ks = 0; ks < 4; ++ks) {
        const int k0 = ks * 16;
        uint32_t a[MF][4], b[NF][2];
#pragma unroll
        for (int mf = 0; mf < MF; ++mf) {
            uint32_t addr = smem_u32(AsH + (size_t)(wrow + mf * 16 + l15) * KPh
                                         + a_off + k0 + lg * 8);
            ldsm_x4(a[mf], addr);
        }
#pragma unroll
        for (int nf = 0; nf < NF; ++nf) {
            uint32_t addr = smem_u32(WsH + (size_t)(k0 + l15) * WKN + wcol + nf * 8);
            ldsm_x2t(b[nf], addr);
        }
#pragma unroll
        for (int mf = 0; mf < MF; ++mf)
#pragma unroll
            for (int nf = 0; nf < NF; ++nf)
                mma_f16(acc[mf][nf], a[mf], b[nf]);
    }
}

// stage one 64-k W chunk [64 x 128] fp32 row-major -> WsH [k][n] fp16 (coalesced, conflict-free)
__device__ __forceinline__ void stage_w64h(const float* __restrict__ W, __half* WsH, int tid)
{
    for (int i = tid; i < 64 * 32; i += 256) {
        int k = i >> 5, c4 = i & 31;
        float4 v = ((const float4*)W)[i];
        __half2 h01 = __floats2half2_rn(v.x, v.y);
        __half2 h23 = __floats2half2_rn(v.z, v.w);
        *(uint2*)(WsH + (size_t)k * WKN + c4 * 4) =
            make_uint2(*(uint32_t*)&h01, *(uint32_t*)&h23);
    }
}

#define ZACC(acc, MF, NF)                             \
    _Pragma("unroll") for (int mf = 0; mf < MF; ++mf) \
    _Pragma("unroll") for (int nf = 0; nf < NF; ++nf) \
    _Pragma("unroll") for (int j = 0; j < 4; ++j) acc[mf][nf][j] = 0.f;

// epilogue: write acc(+bias) to C as fp16
__device__ __forceinline__ void write_c_h(
    __half* __restrict__ C, const float* __restrict__ bias,
    int row0, int wrow, int wcol, int gid, int tig,
    float acc[2][4][4], int M)
{
#pragma unroll
    for (int nf = 0; nf < 4; ++nf) {
        const int c = wcol + nf * 8 + tig * 2;
        const float b0 = bias[c], b1 = bias[c + 1];
#pragma unroll
        for (int mf = 0; mf < 2; ++mf)
#pragma unroll
            for (int h = 0; h < 2; ++h) {
                const int r = row0 + wrow + mf * 16 + h * 8 + gid;
                if (r < M)
                    *(__half2*)(C + (size_t)r * 128 + c) =
                        __floats2half2_rn(acc[mf][nf][2 * h] + b0, acc[mf][nf][2 * h + 1] + b1);
            }
    }
}

// ---------- fused embed + dual transform (BM=64, 3 CTAs/SM) + acc/den zeroing ----------
__global__ __launch_bounds__(256, 3) void embed_dual(
    const float* __restrict__ x,
    const float* __restrict__ We, const float* __restrict__ be,
    const float* __restrict__ Wl, const float* __restrict__ bl,
    const float* __restrict__ Wr, const float* __restrict__ br,
    float* __restrict__ Hout, __half* __restrict__ Cl, __half* __restrict__ Cr,
    __half* __restrict__ Accz, float* __restrict__ Denz, int M)
{
    extern __shared__ __half shh[];
    __half* AsH = shh;                 // 64 x APD (phase A uses pitch APE)
    __half* WsH = shh + 64 * APD;      // 64 x WKN
    const int tid = threadIdx.x;
    const int row0 = blockIdx.x * 64;

    // zero this block's slice of acc (fp16) and den
    {
        const uint4 z = make_uint4(0u, 0u, 0u, 0u);
        int nrow = min(64, M - row0);
        for (int i = tid; i < nrow * 16; i += 256)
            ((uint4*)Accz)[(size_t)row0 * 16 + i] = z;
        if (tid < nrow) Denz[row0 + tid] = 0.f;
    }

    // phase A: stage We [k][n] fp16 + x (fp16, pitch APE)
    stage_w64h(We, WsH, tid);
    for (int i = tid; i < 64 * 16; i += 256) {
        int r = i >> 4, c4 = i & 15;
        int gr = row0 + r;
        float4 v = make_float4(0.f, 0.f, 0.f, 0.f);
        if (gr < M) v = ((const float4*)(x + (size_t)gr * 64))[c4];
        __half2 h01 = __floats2half2_rn(v.x, v.y);
        __half2 h23 = __floats2half2_rn(v.z, v.w);
        *(uint2*)(AsH + (size_t)r * APE + c4 * 4) =
            make_uint2(*(uint32_t*)&h01, *(uint32_t*)&h23);
    }
    __syncthreads();

    const int wid = tid >> 5, lane = tid & 31;
    const int wm = wid & 1, wn = wid >> 1;          // 2x4 warp grid, tile 32x32
    const int wrow = wm * 32, wcol = wn * 32;
    const int gid = lane >> 2, tig = lane & 3;

    float acc[2][4][4];
    ZACC(acc, 2, 4)
    mma_chunk64h<2, 4>(AsH, APE, 0, WsH, wrow, wcol, lane, acc);
    __syncthreads();   // phase-A reads complete before AsH/WsH overwrite

    // epilogue h: write gmem fp32 + restage fp16 into AsH (pitch APD)
#pragma unroll
    for (int nf = 0; nf < 4; ++nf) {
        const int c = wcol + nf * 8 + tig * 2;
        const float b0 = be[c], b1 = be[c + 1];
#pragma unroll
        for (int mf = 0; mf < 2; ++mf)
#pragma unroll
            for (int h = 0; h < 2; ++h) {
                const int rl = wrow + mf * 16 + h * 8 + gid;
                const float v0 = acc[mf][nf][2 * h] + b0;
                const float v1 = acc[mf][nf][2 * h + 1] + b1;
                const int gr = row0 + rl;
                if (gr < M)
                    *(float2*)(Hout + (size_t)gr * 128 + c) = make_float2(v0, v1);
                *(__half2*)(AsH + (size_t)rl * APD + c) = __floats2half2_rn(v0, v1);
            }
    }

#pragma unroll
    for (int ph = 0; ph < 2; ++ph) {
        const float* W    = ph ? Wr : Wl;
        const float* bias = ph ? br : bl;
        __half* C         = ph ? Cr : Cl;
        ZACC(acc, 2, 4)
#pragma unroll
        for (int kc = 0; kc < 2; ++kc) {
            __syncthreads();
            stage_w64h(W + (size_t)kc * 64 * 128, WsH, tid);
            __syncthreads();
            mma_chunk64h<2, 4>(AsH, APD, kc * 64, WsH, wrow, wcol, lane, acc);
        }
        write_c_h(C, bias, row0, wrow, wcol, gid, tig, acc, M);
    }
}

// ---------- dual transform with fused update + zero-after-read (BM=64, 3 CTAs/SM) ----------
__global__ __launch_bounds__(256, 3) void dual_upd(
    float* __restrict__ H, __half* __restrict__ Acc, float* __restrict__ Den,
    const float* __restrict__ ubias,
    const float* __restrict__ Wl, const float* __restrict__ bl,
    const float* __restrict__ Wr, const float* __restrict__ br,
    __half* __restrict__ Cl, __half* __restrict__ Cr, int M)
{
    extern __shared__ __half shh[];
    __half* AsH = shh;                 // 64 x APD
    __half* WsH = shh + 64 * APD;      // 64 x WKN
    const int tid = threadIdx.x;
    const int row0 = blockIdx.x * 64;

    // stage A with fused update: h1 = h + relu(acc/den + ubias)
    for (int i = tid; i < 64 * 32; i += 256) {
        int r = i >> 5, c4 = i & 31;
        int gr = row0 + r;
        float4 hv = make_float4(0.f, 0.f, 0.f, 0.f);
        if (gr < M) {
            float inv = 1.f / (Den[gr] + 1e-16f);
            const __half2* ah = (const __half2*)Acc + (size_t)gr * 64 + c4 * 2;
            float2 a01 = __half22float2(ah[0]);
            float2 a23 = __half22float2(ah[1]);
            hv = ((const float4*)H)[(size_t)gr * 32 + c4];
            const float4 bb = ((const float4*)ubias)[c4];
            hv.x += fmaxf(a01.x * inv + bb.x, 0.f);
            hv.y += fmaxf(a01.y * inv + bb.y, 0.f);
            hv.z += fmaxf(a23.x * inv + bb.z, 0.f);
            hv.w += fmaxf(a23.y * inv + bb.w, 0.f);
            ((float4*)H)[(size_t)gr * 32 + c4] = hv;
        }
        __half2 h01 = __floats2half2_rn(hv.x, hv.y);
        __half2 h23 = __floats2half2_rn(hv.z, hv.w);
        *(uint2*)(AsH + (size_t)r * APD + c4 * 4) =
            make_uint2(*(uint32_t*)&h01, *(uint32_t*)&h23);
    }
    __syncthreads();   // ALL acc/den reads for this block's rows complete

    // zero-after-read: re-zero acc/den for the next edge pass
    {
        const uint4 z = make_uint4(0u, 0u, 0u, 0u);
        int nrow = min(64, M - row0);
        for (int i = tid; i < nrow * 16; i += 256)
            ((uint4*)Acc)[(size_t)row0 * 16 + i] = z;
        if (tid < nrow) Den[row0 + tid] = 0.f;
    }

    const int wid = tid >> 5, lane = tid & 31;
    const int wm = wid & 1, wn = wid >> 1;
    const int wrow = wm * 32, wcol = wn * 32;
    const int gid = lane >> 2, tig = lane & 3;

    float acc[2][4][4];
#pragma unroll
    for (int ph = 0; ph < 2; ++ph) {
        const float* W    = ph ? Wr : Wl;
        const float* bias = ph ? br : bl;
        __half* C         = ph ? Cr : Cl;
        ZACC(acc, 2, 4)
#pragma unroll
        for (int kc = 0; kc < 2; ++kc) {
            __syncthreads();
            stage_w64h(W + (size_t)kc * 64 * 128, WsH, tid);
            __syncthreads();
            mma_chunk64h<2, 4>(AsH, APD, kc * 64, WsH, wrow, wcol, lane, acc);
        }
        write_c_h(C, bias, row0, wrow, wcol, gid, tig, acc, M);
    }
}

// ---------- fused edge pass: warp per edge, fp16 xl/xr/acc ----------
__global__ void edge_kernel(const int* __restrict__ src, const int* __restrict__ dst,
                            const float* __restrict__ att)
{
    int e = (int)(((size_t)blockIdx.x * blockDim.x + threadIdx.x) >> 5);
    if (e >= NE) return;
    int ln = threadIdx.x & 31;
    int s = src[e], d = dst[e];
    const __half2* xap = (const __half2*)g_xl + (size_t)s * 64 + ln * 2;
    const __half2* xbp = (const __half2*)g_xr + (size_t)d * 64 + ln * 2;
    __half2 xa2[2], xb2[2];
    *(uint2*)xa2 = *(const uint2*)xap;
    *(uint2*)xb2 = *(const uint2*)xbp;
    float2 xa01 = __half22float2(xa2[0]);
    float2 xa23 = __half22float2(xa2[1]);
    float2 xb01 = __half22float2(xb2[0]);
    float2 xb23 = __half22float2(xb2[1]);
    float4 at = ((const float4*)att)[ln];

    float vx = xa01.x + xb01.x; vx = vx > 0.f ? vx : 0.2f * vx;
    float vy = xa01.y + xb01.y; vy = vy > 0.f ? vy : 0.2f * vy;
    float vz = xa23.x + xb23.x; vz = vz > 0.f ? vz : 0.2f * vz;
    float vw = xa23.y + xb23.y; vw = vw > 0.f ? vw : 0.2f * vw;
    float p = vx * at.x + vy * at.y + vz * at.z + vw * at.w;
#pragma unroll
    for (int o = 16; o > 0; o >>= 1) p += __shfl_xor_sync(0xffffffffu, p, o);
    float e_ = __expf(p);
    if (ln == 0) atomicAdd(&g_den[d], e_);
    __half2* accd = (__half2*)g_acc + (size_t)d * 64 + ln * 2;
    atomicAdd(accd + 0, __floats2half2_rn(e_ * xa01.x, e_ * xa01.y));
    atomicAdd(accd + 1, __floats2half2_rn(e_ * xa23.x, e_ * xa23.y));
}

// ---------- mega head: BM=64, warp tile 32x32 grid 2x4, 2 CTAs/SM ----------
__global__ __launch_bounds__(256, 2) void head_kernel(
    const float* __restrict__ H, const __half* __restrict__ Acc, const float* __restrict__ Den,
    const float* __restrict__ ubias,
    const int* __restrict__ child, const int* __restrict__ parent,
    const float* __restrict__ ttab, const int* __restrict__ timei,
    const float* __restrict__ W_comb, const float* __restrict__ b_comb,
    const float* __restrict__ W_a1, const float* __restrict__ cadd,
    const float* __restrict__ W_a2, const float* __restrict__ b_a2,
    float* __restrict__ out, int M)
{
    extern __shared__ __half shh[];
    __half* AsH = shh;                       // 64 x APHD
    __half* WsH = shh + 64 * APHD;           // 64 x WKN
    float*  red = (float*)(WsH + 64 * WKN);  // 4 x 64
    const int tid = threadIdx.x;
    const int row0 = blockIdx.x * 64;

    // stage cat(h2[child], h2[parent]|0), h2 = h1 + relu(acc/den + ubias)
    for (int i = tid; i < 64 * 64; i += 256) {
        int r = i >> 6, c4 = i & 63;
        int gr = row0 + r;
        float4 v = make_float4(0.f, 0.f, 0.f, 0.f);
        if (gr < M) {
            int cc = c4 < 32 ? c4 : c4 - 32;
            int ri = c4 < 32 ? child[gr] : parent[gr];
            if (ri >= 0) {
                float inv = 1.f / (Den[ri] + 1e-16f);
                const __half2* ah = (const __half2*)Acc + (size_t)ri * 64 + cc * 2;
                float2 a01 = __half22float2(ah[0]);
                float2 a23 = __half22float2(ah[1]);
                v = ((const float4*)H)[(size_t)ri * 32 + cc];
                float4 bb = ((const float4*)ubias)[cc];
                v.x += fmaxf(a01.x * inv + bb.x, 0.f);
                v.y += fmaxf(a01.y * inv + bb.y, 0.f);
                v.z += fmaxf(a23.x * inv + bb.z, 0.f);
                v.w += fmaxf(a23.y * inv + bb.w, 0.f);
            }
        }
        __half2 h01 = __floats2half2_rn(v.x, v.y);
        __half2 h23 = __floats2half2_rn(v.z, v.w);
        *(uint2*)(AsH + (size_t)r * APHD + c4 * 4) =
            make_uint2(*(uint32_t*)&h01, *(uint32_t*)&h23);
    }

    const int wid = tid >> 5, lane = tid & 31;
    const int wm = wid & 1, wn = wid >> 1;        // 2x4 warp grid, tile 32x32
    const int wrow = wm * 32, wcol = wn * 32;
    const int gid = lane >> 2, tig = lane & 3;

    float acc[2][4][4];
    ZACC(acc, 2, 4)

    // GEMM1: branch = cat @ W_comb  (K=256, 4 chunks)
#pragma unroll
    for (int kc = 0; kc < 4; ++kc) {
        __syncthreads();
        stage_w64h(W_comb + (size_t)kc * 64 * 128, WsH, tid);
        __syncthreads();
        mma_chunk64h<2, 4>(AsH, APHD, kc * 64, WsH, wrow, wcol, lane, acc);
    }
    __syncthreads();   // GEMM1 AsH reads complete before overwrite

    // epilogue1: branch(+b_comb) -> AsH cols [0,128)
#pragma unroll
    for (int nf = 0; nf < 4; ++nf) {
        const int c = wcol + nf * 8 + tig * 2;
        const float b0 = b_comb[c], b1 = b_comb[c + 1];
#pragma unroll
        for (int mf = 0; mf < 2; ++mf)
#pragma unroll
            for (int h = 0; h < 2; ++h) {
                const int rl = wrow + mf * 16 + h * 8 + gid;
                *(__half2*)(AsH + (size_t)rl * APHD + c) =
                    __floats2half2_rn(acc[mf][nf][2 * h] + b0, acc[mf][nf][2 * h + 1] + b1);
            }
    }
    // stage t_emb -> AsH cols [128,256)
    for (int i = tid; i < 64 * 32; i += 256) {
        int r = i >> 5, c4 = i & 31;
        int gr = row0 + r;
        float4 v = make_float4(0.f, 0.f, 0.f, 0.f);
        if (gr < M) {
            int t = timei[gr];
            v = ((const float4*)(ttab + (size_t)t * 128))[c4];
        }
        __half2 h01 = __floats2half2_rn(v.x, v.y);
        __half2 h23 = __floats2half2_rn(v.z, v.w);
        *(uint2*)(AsH + (size_t)r * APHD + 128 + c4 * 4) =
            make_uint2(*(uint32_t*)&h01, *(uint32_t*)&h23);
    }

    // GEMM2: hidden = relu(cat @ W_a1 + cadd)
    ZACC(acc, 2, 4)
#pragma unroll
    for (int kc = 0; kc < 4; ++kc) {
        __syncthreads();
        stage_w64h(W_a1 + (size_t)kc * 64 * 128, WsH, tid);
        __syncthreads();
        mma_chunk64h<2, 4>(AsH, APHD, kc * 64, WsH, wrow, wcol, lane, acc);
    }

    // epilogue2: dot with W_a2
    float p[2][2] = {{0.f, 0.f}, {0.f, 0.f}};
#pragma unroll
    for (int nf = 0; nf < 4; ++nf) {
        const int c = wcol + nf * 8 + tig * 2;
        const float ca0 = cadd[c], ca1 = cadd[c + 1];
        const float w20 = W_a2[c], w21 = W_a2[c + 1];
#pragma unroll
        for (int mf = 0; mf < 2; ++mf)
#pragma unroll
            for (int h = 0; h < 2; ++h) {
                float v0 = fmaxf(acc[mf][nf][2 * h]     + ca0, 0.f);
                float v1 = fmaxf(acc[mf][nf][2 * h + 1] + ca1, 0.f);
                p[mf][h] += v0 * w20 + v1 * w21;
            }
    }
#pragma unroll
    for (int o = 1; o <= 2; o <<= 1)
#pragma unroll
        for (int mf = 0; mf < 2; ++mf)
#pragma unroll
            for (int h = 0; h < 2; ++h)
                p[mf][h] += __shfl_xor_sync(0xffffffffu, p[mf][h], o);

    __syncthreads();
    if (tig == 0) {
#pragma unroll
        for (int mf = 0; mf < 2; ++mf)
#pragma unroll
            for (int h = 0; h < 2; ++h)
                red[wn * 64 + wrow + mf * 16 + h * 8 + gid] = p[mf][h];
    }
    __syncthreads();
    if (tid < 64) {
        int gr = row0 + tid;
        if (gr < M)
            out[gr] = red[tid] + red[64 + tid] + red[128 + tid] + red[192 + tid] + b_a2[0];
    }
}

// ---------------- fused context precompute ----------------
__global__ void ctx_cadd_kernel(const float* __restrict__ focal, const float* __restrict__ W_seq,
                                const float* __restrict__ b_seq,
                                const float* __restrict__ W_a1, const float* __restrict__ b_a1)
{
    __shared__ float cs[128];
    int j = threadIdx.x;
    float s = b_seq[j];
    for (int d = 0; d < DD; ++d) s += focal[d] * W_seq[d * 128 + j];
    cs[j] = s;
    __syncthreads();
    float t = b_a1[j];
    for (int k = 0; k < 128; ++k) t += cs[k] * W_a1[(256 + k) * 128 + j];
    g_cadd[j] = t;
}

// ---------------- launch ----------------
extern "C" void kernel_launch(void* const* d_in, const int* in_sizes, int n_in,
                              void* d_out, int out_size)
{
    const float* x       = (const float*)d_in[0];
    const int*   ei      = (const int*)  d_in[1];
    const float* focal   = (const float*)d_in[2];
    const int*   child   = (const int*)  d_in[3];
    const int*   parent  = (const int*)  d_in[4];
    const int*   timei   = (const int*)  d_in[5];
    const float* W_embed = (const float*)d_in[6];
    const float* b_embed = (const float*)d_in[7];
    const float* bu_Wl   = (const float*)d_in[8];
    const float* bu_bl   = (const float*)d_in[9];
    const float* bu_Wr   = (const float*)d_in[10];
    const float* bu_br   = (const float*)d_in[11];
    const float* bu_att  = (const float*)d_in[12];
    const float* bu_bias = (const float*)d_in[13];
    const float* td_Wl   = (const float*)d_in[14];
    const float* td_bl   = (const float*)d_in[15];
    const float* td_Wr   = (const float*)d_in[16];
    const float* td_br   = (const float*)d_in[17];
    const float* td_att  = (const float*)d_in[18];
    const float* td_bias = (const float*)d_in[19];
    const float* ttab    = (const float*)d_in[20];
    const float* W_comb  = (const float*)d_in[21];
    const float* b_comb  = (const float*)d_in[22];
    const float* W_a1    = (const float*)d_in[23];
    const float* b_a1    = (const float*)d_in[24];
    const float* W_a2    = (const float*)d_in[25];
    const float* b_a2    = (const float*)d_in[26];
    const float* W_seq   = (const float*)d_in[27];
    const float* b_seq   = (const float*)d_in[28];
    float* out = (float*)d_out;

    const int SM_DUAL = (64 * APD + 64 * WKN) * 2;                // 34,816 B (3 CTAs/SM)
    const int SM_HEAD = (64 * APHD + 64 * WKN) * 2 + 256 * 4;     // 52,224 B (2 CTAs/SM)
    cudaFuncSetAttribute(embed_dual,  cudaFuncAttributeMaxDynamicSharedMemorySize, SM_DUAL);
    cudaFuncSetAttribute(dual_upd,    cudaFuncAttributeMaxDynamicSharedMemorySize, SM_DUAL);
    cudaFuncSetAttribute(head_kernel, cudaFuncAttributeMaxDynamicSharedMemorySize, SM_HEAD);

    float *hp, *denp, *caddp;
    __half *xlp, *xrp, *accp;
    cudaGetSymbolAddress((void**)&hp,    g_h);
    cudaGetSymbolAddress((void**)&xlp,   g_xl);
    cudaGetSymbolAddress((void**)&xrp,   g_xr);
    cudaGetSymbolAddress((void**)&accp,  g_acc);
    cudaGetSymbolAddress((void**)&denp,  g_den);
    cudaGetSymbolAddress((void**)&caddp, g_cadd);

    const int GEMM_BLKS_N = (NN + 63) / 64;
    const int HEAD_BLKS   = (NA + 63) / 64;
    const int EDGE_BLKS   = (NE + 7) / 8;

    // 0) context fold (tiny, no deps on pipeline)
    ctx_cadd_kernel<<<1, 128>>>(focal, W_seq, b_seq, W_a1, b_a1);

    // 1) embed + bottom-up transforms + acc/den zeroing (src = row1, dst = row0)
    embed_dual<<<GEMM_BLKS_N, 256, SM_DUAL>>>(x, W_embed, b_embed,
                                              bu_Wl, bu_bl, bu_Wr, bu_br,
                                              hp, xlp, xrp, accp, denp, NN);
    edge_kernel<<<EDGE_BLKS, 256>>>(ei + NE, ei, bu_att);

    // 2) update1 fused + top-down transforms + zero-after-read (src = row0, dst = row1)
    dual_upd<<<GEMM_BLKS_N, 256, SM_DUAL>>>(hp, accp, denp, bu_bias,
                                            td_Wl, td_bl, td_Wr, td_br,
                                            xlp, xrp, NN);
    edge_kernel<<<EDGE_BLKS, 256>>>(ei, ei + NE, td_att);

    // 3) head with on-the-fly update2
    head_kernel<<<HEAD_BLKS, 256, SM_HEAD>>>(hp, accp, denp, td_bias,
                                             child, parent, ttab, timei,
                                             W_comb, b_comb, W_a1, caddp,
                                             W_a2, b_a2, out, NA);
}

// round 15
// speedup vs baseline: 1.3059x; 1.0167x over previous
#include <cuda_runtime.h>
#include <cuda_fp16.h>
#include <math.h>
#include <stdint.h>

#define NN   300000
#define NE   299999
#define NA   150000
#define DD   64
#define HH   128

// ---------------- scratch ----------------
__device__ __half g_h   [(size_t)NN * HH];
__device__ __half g_xl  [(size_t)NN * HH];
__device__ __half g_xr  [(size_t)NN * HH];
__device__ __half g_acc [(size_t)NN * HH];
__device__ float  g_den [NN];
__device__ float  g_cadd[HH];

// ---------------- helpers ----------------
__device__ __forceinline__ uint32_t smem_u32(const void* p)
{
    uint32_t a;
    asm("{ .reg .u64 t; cvta.to.shared.u64 t, %1; cvt.u32.u64 %0, t; }" : "=r"(a) : "l"(p));
    return a;
}

__device__ __forceinline__ void mma_f16(float* d, const uint32_t* a, const uint32_t* b)
{
    asm volatile(
        "mma.sync.aligned.m16n8k16.row.col.f32.f16.f16.f32 "
        "{%0,%1,%2,%3},{%4,%5,%6,%7},{%8,%9},{%0,%1,%2,%3};"
        : "+f"(d[0]), "+f"(d[1]), "+f"(d[2]), "+f"(d[3])
        : "r"(a[0]), "r"(a[1]), "r"(a[2]), "r"(a[3]), "r"(b[0]), "r"(b[1]));
}

__device__ __forceinline__ void ldsm_x4(uint32_t* r, uint32_t addr)
{
    asm volatile("ldmatrix.sync.aligned.m8n8.x4.shared.b16 {%0,%1,%2,%3}, [%4];"
                 : "=r"(r[0]), "=r"(r[1]), "=r"(r[2]), "=r"(r[3]) : "r"(addr));
}
__device__ __forceinline__ void ldsm_x2t(uint32_t* r, uint32_t addr)
{
    asm volatile("ldmatrix.sync.aligned.m8n8.x2.trans.shared.b16 {%0,%1}, [%2];"
                 : "=r"(r[0]), "=r"(r[1]) : "r"(addr));
}

// pitches in halves; all give row pitch ≡ 4 words mod 32 -> ldmatrix conflict-free
#define WKN  136     // W smem [k][n] pitch (n=128+8)
#define APE  72      // A pitch (K=64)
#define APD  136     // A pitch (K=128)
#define APHD 264     // A pitch (K=256, head)

// fp16 mainloop over one 64-k chunk (4 mma k-steps). Warp tile (MF*16) x (NF*8).
template <int MF, int NF>
__device__ __forceinline__ void mma_chunk64h(
    const __half* AsH, int KPh, int a_off, const __half* WsH,
    int wrow, int wcol, int lane, float acc[MF][NF][4])
{
    const int l15 = lane & 15, lg = lane >> 4;
#pragma unroll
    for (int ks = 0; ks < 4; ++ks) {
        const int k0 = ks * 16;
        uint32_t a[MF][4], b[NF][2];
#pragma unroll
        for (int mf = 0; mf < MF; ++mf) {
            uint32_t addr = smem_u32(AsH + (size_t)(wrow + mf * 16 + l15) * KPh
                                         + a_off + k0 + lg * 8);
            ldsm_x4(a[mf], addr);
        }
#pragma unroll
        for (int nf = 0; nf < NF; ++nf) {
            uint32_t addr = smem_u32(WsH + (size_t)(k0 + l15) * WKN + wcol + nf * 8);
            ldsm_x2t(b[nf], addr);
        }
#pragma unroll
        for (int mf = 0; mf < MF; ++mf)
#pragma unroll
            for (int nf = 0; nf < NF; ++nf)
                mma_f16(acc[mf][nf], a[mf], b[nf]);
    }
}

// stage one 64-k W chunk [64 x 128] fp32 row-major -> WsH [k][n] fp16
__device__ __forceinline__ void stage_w64h(const float* __restrict__ W, __half* WsH, int tid)
{
    for (int i = tid; i < 64 * 32; i += 256) {
        int k = i >> 5, c4 = i & 31;
        float4 v = ((const float4*)W)[i];
        __half2 h01 = __floats2half2_rn(v.x, v.y);
        __half2 h23 = __floats2half2_rn(v.z, v.w);
        *(uint2*)(WsH + (size_t)k * WKN + c4 * 4) =
            make_uint2(*(uint32_t*)&h01, *(uint32_t*)&h23);
    }
}

#define ZACC(acc, MF, NF)                             \
    _Pragma("unroll") for (int mf = 0; mf < MF; ++mf) \
    _Pragma("unroll") for (int nf = 0; nf < NF; ++nf) \
    _Pragma("unroll") for (int j = 0; j < 4; ++j) acc[mf][nf][j] = 0.f;

// epilogue: write acc(+bias) to C as fp16
__device__ __forceinline__ void write_c_h(
    __half* __restrict__ C, const float* __restrict__ bias,
    int row0, int wrow, int wcol, int gid, int tig,
    float acc[2][4][4], int M)
{
#pragma unroll
    for (int nf = 0; nf < 4; ++nf) {
        const int c = wcol + nf * 8 + tig * 2;
        const float b0 = bias[c], b1 = bias[c + 1];
#pragma unroll
        for (int mf = 0; mf < 2; ++mf)
#pragma unroll
            for (int h = 0; h < 2; ++h) {
                const int r = row0 + wrow + mf * 16 + h * 8 + gid;
                if (r < M)
                    *(__half2*)(C + (size_t)r * 128 + c) =
                        __floats2half2_rn(acc[mf][nf][2 * h] + b0, acc[mf][nf][2 * h + 1] + b1);
            }
    }
}

// ---------- fused embed + dual transform (BM=64, 3 CTAs/SM) + acc/den zeroing ----------
__global__ __launch_bounds__(256, 3) void embed_dual(
    const float* __restrict__ x,
    const float* __restrict__ We, const float* __restrict__ be,
    const float* __restrict__ Wl, const float* __restrict__ bl,
    const float* __restrict__ Wr, const float* __restrict__ br,
    __half* __restrict__ Hout, __half* __restrict__ Cl, __half* __restrict__ Cr,
    __half* __restrict__ Accz, float* __restrict__ Denz, int M)
{
    extern __shared__ __half shh[];
    __half* AsH = shh;                 // 64 x APD (phase A uses pitch APE)
    __half* WsH = shh + 64 * APD;      // 64 x WKN
    const int tid = threadIdx.x;
    const int row0 = blockIdx.x * 64;

    // zero this block's slice of acc (fp16) and den
    {
        const uint4 z = make_uint4(0u, 0u, 0u, 0u);
        int nrow = min(64, M - row0);
        for (int i = tid; i < nrow * 16; i += 256)
            ((uint4*)Accz)[(size_t)row0 * 16 + i] = z;
        if (tid < nrow) Denz[row0 + tid] = 0.f;
    }

    // phase A: stage We [k][n] fp16 + x (fp16, pitch APE)
    stage_w64h(We, WsH, tid);
    for (int i = tid; i < 64 * 16; i += 256) {
        int r = i >> 4, c4 = i & 15;
        int gr = row0 + r;
        float4 v = make_float4(0.f, 0.f, 0.f, 0.f);
        if (gr < M) v = ((const float4*)(x + (size_t)gr * 64))[c4];
        __half2 h01 = __floats2half2_rn(v.x, v.y);
        __half2 h23 = __floats2half2_rn(v.z, v.w);
        *(uint2*)(AsH + (size_t)r * APE + c4 * 4) =
            make_uint2(*(uint32_t*)&h01, *(uint32_t*)&h23);
    }
    __syncthreads();

    const int wid = tid >> 5, lane = tid & 31;
    const int wm = wid & 1, wn = wid >> 1;          // 2x4 warp grid, tile 32x32
    const int wrow = wm * 32, wcol = wn * 32;
    const int gid = lane >> 2, tig = lane & 3;

    float acc[2][4][4];
    ZACC(acc, 2, 4)
    mma_chunk64h<2, 4>(AsH, APE, 0, WsH, wrow, wcol, lane, acc);
    __syncthreads();   // phase-A reads complete before AsH/WsH overwrite

    // epilogue h: write gmem fp16 + restage fp16 into AsH (pitch APD)
#pragma unroll
    for (int nf = 0; nf < 4; ++nf) {
        const int c = wcol + nf * 8 + tig * 2;
        const float b0 = be[c], b1 = be[c + 1];
#pragma unroll
        for (int mf = 0; mf < 2; ++mf)
#pragma unroll
            for (int h = 0; h < 2; ++h) {
                const int rl = wrow + mf * 16 + h * 8 + gid;
                const float v0 = acc[mf][nf][2 * h] + b0;
                const float v1 = acc[mf][nf][2 * h + 1] + b1;
                const int gr = row0 + rl;
                __half2 hv = __floats2half2_rn(v0, v1);
                if (gr < M)
                    *(__half2*)(Hout + (size_t)gr * 128 + c) = hv;
                *(__half2*)(AsH + (size_t)rl * APD + c) = hv;
            }
    }

#pragma unroll
    for (int ph = 0; ph < 2; ++ph) {
        const float* W    = ph ? Wr : Wl;
        const float* bias = ph ? br : bl;
        __half* C         = ph ? Cr : Cl;
        ZACC(acc, 2, 4)
#pragma unroll
        for (int kc = 0; kc < 2; ++kc) {
            __syncthreads();
            stage_w64h(W + (size_t)kc * 64 * 128, WsH, tid);
            __syncthreads();
            mma_chunk64h<2, 4>(AsH, APD, kc * 64, WsH, wrow, wcol, lane, acc);
        }
        write_c_h(C, bias, row0, wrow, wcol, gid, tig, acc, M);
    }
}

// ---------- dual transform with fused update + zero-after-read (BM=64, 3 CTAs/SM) ----------
__global__ __launch_bounds__(256, 3) void dual_upd(
    __half* __restrict__ H, __half* __restrict__ Acc, float* __restrict__ Den,
    const float* __restrict__ ubias,
    const float* __restrict__ Wl, const float* __restrict__ bl,
    const float* __restrict__ Wr, const float* __restrict__ br,
    __half* __restrict__ Cl, __half* __restrict__ Cr, int M)
{
    extern __shared__ __half shh[];
    __half* AsH = shh;                 // 64 x APD
    __half* WsH = shh + 64 * APD;      // 64 x WKN
    const int tid = threadIdx.x;
    const int row0 = blockIdx.x * 64;

    // stage A with fused update: h1 = h + relu(acc/den + ubias)
    for (int i = tid; i < 64 * 32; i += 256) {
        int r = i >> 5, c4 = i & 31;
        int gr = row0 + r;
        float4 hv = make_float4(0.f, 0.f, 0.f, 0.f);
        if (gr < M) {
            float inv = 1.f / (Den[gr] + 1e-16f);
            const __half2* ah = (const __half2*)Acc + (size_t)gr * 64 + c4 * 2;
            float2 a01 = __half22float2(ah[0]);
            float2 a23 = __half22float2(ah[1]);
            const __half2* hh = (const __half2*)H + (size_t)gr * 64 + c4 * 2;
            float2 h01 = __half22float2(hh[0]);
            float2 h23 = __half22float2(hh[1]);
            const float4 bb = ((const float4*)ubias)[c4];
            hv.x = h01.x + fmaxf(a01.x * inv + bb.x, 0.f);
            hv.y = h01.y + fmaxf(a01.y * inv + bb.y, 0.f);
            hv.z = h23.x + fmaxf(a23.x * inv + bb.z, 0.f);
            hv.w = h23.y + fmaxf(a23.y * inv + bb.w, 0.f);
            __half2 o01 = __floats2half2_rn(hv.x, hv.y);
            __half2 o23 = __floats2half2_rn(hv.z, hv.w);
            *(uint2*)((__half2*)H + (size_t)gr * 64 + c4 * 2) =
                make_uint2(*(uint32_t*)&o01, *(uint32_t*)&o23);
        }
        __half2 h01 = __floats2half2_rn(hv.x, hv.y);
        __half2 h23 = __floats2half2_rn(hv.z, hv.w);
        *(uint2*)(AsH + (size_t)r * APD + c4 * 4) =
            make_uint2(*(uint32_t*)&h01, *(uint32_t*)&h23);
    }
    __syncthreads();   // ALL acc/den reads for this block's rows complete

    // zero-after-read: re-zero acc/den for the next edge pass
    {
        const uint4 z = make_uint4(0u, 0u, 0u, 0u);
        int nrow = min(64, M - row0);
        for (int i = tid; i < nrow * 16; i += 256)
            ((uint4*)Acc)[(size_t)row0 * 16 + i] = z;
        if (tid < nrow) Den[row0 + tid] = 0.f;
    }

    const int wid = tid >> 5, lane = tid & 31;
    const int wm = wid & 1, wn = wid >> 1;
    const int wrow = wm * 32, wcol = wn * 32;
    const int gid = lane >> 2, tig = lane & 3;

    float acc[2][4][4];
#pragma unroll
    for (int ph = 0; ph < 2; ++ph) {
        const float* W    = ph ? Wr : Wl;
        const float* bias = ph ? br : bl;
        __half* C         = ph ? Cr : Cl;
        ZACC(acc, 2, 4)
#pragma unroll
        for (int kc = 0; kc < 2; ++kc) {
            __syncthreads();
            stage_w64h(W + (size_t)kc * 64 * 128, WsH, tid);
            __syncthreads();
            mma_chunk64h<2, 4>(AsH, APD, kc * 64, WsH, wrow, wcol, lane, acc);
        }
        write_c_h(C, bias, row0, wrow, wcol, gid, tig, acc, M);
    }
}

// ---------- fused edge pass: warp per edge, fp16 xl/xr/acc ----------
__global__ void edge_kernel(const int* __restrict__ src, const int* __restrict__ dst,
                            const float* __restrict__ att)
{
    int e = (int)(((size_t)blockIdx.x * blockDim.x + threadIdx.x) >> 5);
    if (e >= NE) return;
    int ln = threadIdx.x & 31;
    int s = src[e], d = dst[e];
    const __half2* xap = (const __half2*)g_xl + (size_t)s * 64 + ln * 2;
    const __half2* xbp = (const __half2*)g_xr + (size_t)d * 64 + ln * 2;
    __half2 xa2[2], xb2[2];
    *(uint2*)xa2 = *(const uint2*)xap;
    *(uint2*)xb2 = *(const uint2*)xbp;
    float2 xa01 = __half22float2(xa2[0]);
    float2 xa23 = __half22float2(xa2[1]);
    float2 xb01 = __half22float2(xb2[0]);
    float2 xb23 = __half22float2(xb2[1]);
    float4 at = ((const float4*)att)[ln];

    float vx = xa01.x + xb01.x; vx = vx > 0.f ? vx : 0.2f * vx;
    float vy = xa01.y + xb01.y; vy = vy > 0.f ? vy : 0.2f * vy;
    float vz = xa23.x + xb23.x; vz = vz > 0.f ? vz : 0.2f * vz;
    float vw = xa23.y + xb23.y; vw = vw > 0.f ? vw : 0.2f * vw;
    float p = vx * at.x + vy * at.y + vz * at.z + vw * at.w;
#pragma unroll
    for (int o = 16; o > 0; o >>= 1) p += __shfl_xor_sync(0xffffffffu, p, o);
    float e_ = __expf(p);
    if (ln == 0) atomicAdd(&g_den[d], e_);
    __half2* accd = (__half2*)g_acc + (size_t)d * 64 + ln * 2;
    atomicAdd(accd + 0, __floats2half2_rn(e_ * xa01.x, e_ * xa01.y));
    atomicAdd(accd + 1, __floats2half2_rn(e_ * xa23.x, e_ * xa23.y));
}

// ---------- mega head: BM=64, warp tile 32x32 grid 2x4, 2 CTAs/SM ----------
__global__ __launch_bounds__(256, 2) void head_kernel(
    const __half* __restrict__ H, const __half* __restrict__ Acc, const float* __restrict__ Den,
    const float* __restrict__ ubias,
    const int* __restrict__ child, const int* __restrict__ parent,
    const float* __restrict__ ttab, const int* __restrict__ timei,
    const float* __restrict__ W_comb, const float* __restrict__ b_comb,
    const float* __restrict__ W_a1, const float* __restrict__ cadd,
    const float* __restrict__ W_a2, const float* __restrict__ b_a2,
    float* __restrict__ out, int M)
{
    extern __shared__ __half shh[];
    __half* AsH = shh;                       // 64 x APHD
    __half* WsH = shh + 64 * APHD;           // 64 x WKN
    float*  red = (float*)(WsH + 64 * WKN);  // 4 x 64
    const int tid = threadIdx.x;
    const int row0 = blockIdx.x * 64;

    // stage cat(h2[child], h2[parent]|0), h2 = h1 + relu(acc/den + ubias)
    for (int i = tid; i < 64 * 64; i += 256) {
        int r = i >> 6, c4 = i & 63;
        int gr = row0 + r;
        float4 v = make_float4(0.f, 0.f, 0.f, 0.f);
        if (gr < M) {
            int cc = c4 < 32 ? c4 : c4 - 32;
            int ri = c4 < 32 ? child[gr] : parent[gr];
            if (ri >= 0) {
                float inv = 1.f / (Den[ri] + 1e-16f);
                const __half2* ah = (const __half2*)Acc + (size_t)ri * 64 + cc * 2;
                float2 a01 = __half22float2(ah[0]);
                float2 a23 = __half22float2(ah[1]);
                const __half2* hh = (const __half2*)H + (size_t)ri * 64 + cc * 2;
                float2 h01 = __half22float2(hh[0]);
                float2 h23 = __half22float2(hh[1]);
                float4 bb = ((const float4*)ubias)[cc];
                v.x = h01.x + fmaxf(a01.x * inv + bb.x, 0.f);
                v.y = h01.y + fmaxf(a01.y * inv + bb.y, 0.f);
                v.z = h23.x + fmaxf(a23.x * inv + bb.z, 0.f);
                v.w = h23.y + fmaxf(a23.y * inv + bb.w, 0.f);
            }
        }
        __half2 h01 = __floats2half2_rn(v.x, v.y);
        __half2 h23 = __floats2half2_rn(v.z, v.w);
        *(uint2*)(AsH + (size_t)r * APHD + c4 * 4) =
            make_uint2(*(uint32_t*)&h01, *(uint32_t*)&h23);
    }

    const int wid = tid >> 5, lane = tid & 31;
    const int wm = wid & 1, wn = wid >> 1;        // 2x4 warp grid, tile 32x32
    const int wrow = wm * 32, wcol = wn * 32;
    const int gid = lane >> 2, tig = lane & 3;

    float acc[2][4][4];
    ZACC(acc, 2, 4)

    // GEMM1: branch = cat @ W_comb  (K=256, 4 chunks)
#pragma unroll
    for (int kc = 0; kc < 4; ++kc) {
        __syncthreads();
        stage_w64h(W_comb + (size_t)kc * 64 * 128, WsH, tid);
        __syncthreads();
        mma_chunk64h<2, 4>(AsH, APHD, kc * 64, WsH, wrow, wcol, lane, acc);
    }
    __syncthreads();   // GEMM1 AsH reads complete before overwrite

    // epilogue1: branch(+b_comb) -> AsH cols [0,128)
#pragma unroll
    for (int nf = 0; nf < 4; ++nf) {
        const int c = wcol + nf * 8 + tig * 2;
        const float b0 = b_comb[c], b1 = b_comb[c + 1];
#pragma unroll
        for (int mf = 0; mf < 2; ++mf)
#pragma unroll
            for (int h = 0; h < 2; ++h) {
                const int rl = wrow + mf * 16 + h * 8 + gid;
                *(__half2*)(AsH + (size_t)rl * APHD + c) =
                    __floats2half2_rn(acc[mf][nf][2 * h] + b0, acc[mf][nf][2 * h + 1] + b1);
            }
    }
    // stage t_emb -> AsH cols [128,256)
    for (int i = tid; i < 64 * 32; i += 256) {
        int r = i >> 5, c4 = i & 31;
        int gr = row0 + r;
        float4 v = make_float4(0.f, 0.f, 0.f, 0.f);
        if (gr < M) {
            int t = timei[gr];
            v = ((const float4*)(ttab + (size_t)t * 128))[c4];
        }
        __half2 h01 = __floats2half2_rn(v.x, v.y);
        __half2 h23 = __floats2half2_rn(v.z, v.w);
        *(uint2*)(AsH + (size_t)r * APHD + 128 + c4 * 4) =
            make_uint2(*(uint32_t*)&h01, *(uint32_t*)&h23);
    }

    // GEMM2: hidden = relu(cat @ W_a1 + cadd)
    ZACC(acc, 2, 4)
#pragma unroll
    for (int kc = 0; kc < 4; ++kc) {
        __syncthreads();
        stage_w64h(W_a1 + (size_t)kc * 64 * 128, WsH, tid);
        __syncthreads();
        mma_chunk64h<2, 4>(AsH, APHD, kc * 64, WsH, wrow, wcol, lane, acc);
    }

    // epilogue2: dot with W_a2
    float p[2][2] = {{0.f, 0.f}, {0.f, 0.f}};
#pragma unroll
    for (int nf = 0; nf < 4; ++nf) {
        const int c = wcol + nf * 8 + tig * 2;
        const float ca0 = cadd[c], ca1 = cadd[c + 1];
        const float w20 = W_a2[c], w21 = W_a2[c + 1];
#pragma unroll
        for (int mf = 0; mf < 2; ++mf)
#pragma unroll
            for (int h = 0; h < 2; ++h) {
                float v0 = fmaxf(acc[mf][nf][2 * h]     + ca0, 0.f);
                float v1 = fmaxf(acc[mf][nf][2 * h + 1] + ca1, 0.f);
                p[mf][h] += v0 * w20 + v1 * w21;
            }
    }
#pragma unroll
    for (int o = 1; o <= 2; o <<= 1)
#pragma unroll
        for (int mf = 0; mf < 2; ++mf)
#pragma unroll
            for (int h = 0; h < 2; ++h)
                p[mf][h] += __shfl_xor_sync(0xffffffffu, p[mf][h], o);

    __syncthreads();
    if (tig == 0) {
#pragma unroll
        for (int mf = 0; mf < 2; ++mf)
#pragma unroll
            for (int h = 0; h < 2; ++h)
                red[wn * 64 + wrow + mf * 16 + h * 8 + gid] = p[mf][h];
    }
    __syncthreads();
    if (tid < 64) {
        int gr = row0 + tid;
        if (gr < M)
            out[gr] = red[tid] + red[64 + tid] + red[128 + tid] + red[192 + tid] + b_a2[0];
    }
}

// ---------------- fused context precompute ----------------
__global__ void ctx_cadd_kernel(const float* __restrict__ focal, const float* __restrict__ W_seq,
                                const float* __restrict__ b_seq,
                                const float* __restrict__ W_a1, const float* __restrict__ b_a1)
{
    __shared__ float cs[128];
    int j = threadIdx.x;
    float s = b_seq[j];
    for (int d = 0; d < DD; ++d) s += focal[d] * W_seq[d * 128 + j];
    cs[j] = s;
    __syncthreads();
    float t = b_a1[j];
    for (int k = 0; k < 128; ++k) t += cs[k] * W_a1[(256 + k) * 128 + j];
    g_cadd[j] = t;
}

// ---------------- launch ----------------
extern "C" void kernel_launch(void* const* d_in, const int* in_sizes, int n_in,
                              void* d_out, int out_size)
{
    const float* x       = (const float*)d_in[0];
    const int*   ei      = (const int*)  d_in[1];
    const float* focal   = (const float*)d_in[2];
    const int*   child   = (const int*)  d_in[3];
    const int*   parent  = (const int*)  d_in[4];
    const int*   timei   = (const int*)  d_in[5];
    const float* W_embed = (const float*)d_in[6];
    const float* b_embed = (const float*)d_in[7];
    const float* bu_Wl   = (const float*)d_in[8];
    const float* bu_bl   = (const float*)d_in[9];
    const float* bu_Wr   = (const float*)d_in[10];
    const float* bu_br   = (const float*)d_in[11];
    const float* bu_att  = (const float*)d_in[12];
    const float* bu_bias = (const float*)d_in[13];
    const float* td_Wl   = (const float*)d_in[14];
    const float* td_bl   = (const float*)d_in[15];
    const float* td_Wr   = (const float*)d_in[16];
    const float* td_br   = (const float*)d_in[17];
    const float* td_att  = (const float*)d_in[18];
    const float* td_bias = (const float*)d_in[19];
    const float* ttab    = (const float*)d_in[20];
    const float* W_comb  = (const float*)d_in[21];
    const float* b_comb  = (const float*)d_in[22];
    const float* W_a1    = (const float*)d_in[23];
    const float* b_a1    = (const float*)d_in[24];
    const float* W_a2    = (const float*)d_in[25];
    const float* b_a2    = (const float*)d_in[26];
    const float* W_seq   = (const float*)d_in[27];
    const float* b_seq   = (const float*)d_in[28];
    float* out = (float*)d_out;

    const int SM_DUAL = (64 * APD + 64 * WKN) * 2;                // 34,816 B (3 CTAs/SM)
    const int SM_HEAD = (64 * APHD + 64 * WKN) * 2 + 256 * 4;     // 52,224 B (2 CTAs/SM)
    cudaFuncSetAttribute(embed_dual,  cudaFuncAttributeMaxDynamicSharedMemorySize, SM_DUAL);
    cudaFuncSetAttribute(dual_upd,    cudaFuncAttributeMaxDynamicSharedMemorySize, SM_DUAL);
    cudaFuncSetAttribute(head_kernel, cudaFuncAttributeMaxDynamicSharedMemorySize, SM_HEAD);

    float *denp, *caddp;
    __half *hp, *xlp, *xrp, *accp;
    cudaGetSymbolAddress((void**)&hp,    g_h);
    cudaGetSymbolAddress((void**)&xlp,   g_xl);
    cudaGetSymbolAddress((void**)&xrp,   g_xr);
    cudaGetSymbolAddress((void**)&accp,  g_acc);
    cudaGetSymbolAddress((void**)&denp,  g_den);
    cudaGetSymbolAddress((void**)&caddp, g_cadd);

    const int GEMM_BLKS_N = (NN + 63) / 64;
    const int HEAD_BLKS   = (NA + 63) / 64;
    const int EDGE_BLKS   = (NE + 7) / 8;

    // 0) context fold (tiny, no deps on pipeline)
    ctx_cadd_kernel<<<1, 128>>>(focal, W_seq, b_seq, W_a1, b_a1);

    // 1) embed + bottom-up transforms + acc/den zeroing (src = row1, dst = row0)
    embed_dual<<<GEMM_BLKS_N, 256, SM_DUAL>>>(x, W_embed, b_embed,
                                              bu_Wl, bu_bl, bu_Wr, bu_br,
                                              hp, xlp, xrp, accp, denp, NN);
    edge_kernel<<<EDGE_BLKS, 256>>>(ei + NE, ei, bu_att);

    // 2) update1 fused + top-down transforms + zero-after-read (src = row0, dst = row1)
    dual_upd<<<GEMM_BLKS_N, 256, SM_DUAL>>>(hp, accp, denp, bu_bias,
                                            td_Wl, td_bl, td_Wr, td_br,
                                            xlp, xrp, NN);
    edge_kernel<<<EDGE_BLKS, 256>>>(ei, ei + NE, td_att);

    // 3) head with on-the-fly update2
    head_kernel<<<HEAD_BLKS, 256, SM_HEAD>>>(hp, accp, denp, td_bias,
                                             child, parent, ttab, timei,
                                             W_comb, b_comb, W_a1, caddp,
                                             W_a2, b_a2, out, NA);
}

// round 16
// speedup vs baseline: 1.4362x; 1.0997x over previous
#include <cuda_runtime.h>
#include <cuda_fp16.h>
#include <math.h>
#include <stdint.h>

#define NN   300000
#define NE   299999
#define NA   150000
#define DD   64
#define HH   128

// ---------------- scratch ----------------
__device__ __half g_h   [(size_t)NN * HH];
__device__ __half g_xl  [(size_t)NN * HH];
__device__ __half g_xr  [(size_t)NN * HH];
__device__ __half g_acc [(size_t)NN * HH];
__device__ float  g_den [NN];
__device__ float  g_cadd[HH];

// fp16 pre-converted weights, dense [k][128]
#define OFF_WE    0
#define OFF_BUWL  8192
#define OFF_BUWR  24576
#define OFF_TDWL  40960
#define OFF_TDWR  57344
#define OFF_WCOMB 73728
#define OFF_WA1   106496
__device__ __align__(16) __half g_wh[139264];

// ---------------- helpers ----------------
__device__ __forceinline__ uint32_t smem_u32(const void* p)
{
    uint32_t a;
    asm("{ .reg .u64 t; cvta.to.shared.u64 t, %1; cvt.u32.u64 %0, t; }" : "=r"(a) : "l"(p));
    return a;
}

__device__ __forceinline__ void mma_f16(float* d, const uint32_t* a, const uint32_t* b)
{
    asm volatile(
        "mma.sync.aligned.m16n8k16.row.col.f32.f16.f16.f32 "
        "{%0,%1,%2,%3},{%4,%5,%6,%7},{%8,%9},{%0,%1,%2,%3};"
        : "+f"(d[0]), "+f"(d[1]), "+f"(d[2]), "+f"(d[3])
        : "r"(a[0]), "r"(a[1]), "r"(a[2]), "r"(a[3]), "r"(b[0]), "r"(b[1]));
}

__device__ __forceinline__ void ldsm_x4(uint32_t* r, uint32_t addr)
{
    asm volatile("ldmatrix.sync.aligned.m8n8.x4.shared.b16 {%0,%1,%2,%3}, [%4];"
                 : "=r"(r[0]), "=r"(r[1]), "=r"(r[2]), "=r"(r[3]) : "r"(addr));
}
__device__ __forceinline__ void ldsm_x2t(uint32_t* r, uint32_t addr)
{
    asm volatile("ldmatrix.sync.aligned.m8n8.x2.trans.shared.b16 {%0,%1}, [%2];"
                 : "=r"(r[0]), "=r"(r[1]) : "r"(addr));
}

__device__ __forceinline__ void cp_async16(uint32_t saddr, const void* g)
{
    asm volatile("cp.async.cg.shared.global [%0], [%1], 16;" :: "r"(saddr), "l"(g));
}
#define CP_COMMIT() asm volatile("cp.async.commit_group;")
#define CP_WAIT0()  asm volatile("cp.async.wait_group 0;")

// pitches in halves; row pitch ≡ 4 words mod 32 -> ldmatrix conflict-free
#define WKN  136     // W smem [k][n] pitch
#define APE  72      // A pitch (K=64)
#define APD  136     // A pitch (K=128)
#define APHD 264     // A pitch (K=256, head)

// fp16 mainloop over one 64-k chunk (4 mma k-steps). Warp tile (MF*16) x (NF*8).
template <int MF, int NF>
__device__ __forceinline__ void mma_chunk64h(
    const __half* AsH, int KPh, int a_off, const __half* WsH,
    int wrow, int wcol, int lane, float acc[MF][NF][4])
{
    const int l15 = lane & 15, lg = lane >> 4;
#pragma unroll
    for (int ks = 0; ks < 4; ++ks) {
        const int k0 = ks * 16;
        uint32_t a[MF][4], b[NF][2];
#pragma unroll
        for (int mf = 0; mf < MF; ++mf) {
            uint32_t addr = smem_u32(AsH + (size_t)(wrow + mf * 16 + l15) * KPh
                                         + a_off + k0 + lg * 8);
            ldsm_x4(a[mf], addr);
        }
#pragma unroll
        for (int nf = 0; nf < NF; ++nf) {
            uint32_t addr = smem_u32(WsH + (size_t)(k0 + l15) * WKN + wcol + nf * 8);
            ldsm_x2t(b[nf], addr);
        }
#pragma unroll
        for (int mf = 0; mf < MF; ++mf)
#pragma unroll
            for (int nf = 0; nf < NF; ++nf)
                mma_f16(acc[mf][nf], a[mf], b[nf]);
    }
}

// async-stage one 64-k fp16 W chunk (dense [64][128]) -> WsH [k][n] pitch WKN
__device__ __forceinline__ void stage_w_async(const __half* __restrict__ Wsrc,
                                              __half* WsH, int tid)
{
    for (int i = tid; i < 1024; i += 256) {
        int k = i >> 4, c8 = i & 15;
        cp_async16(smem_u32(WsH + (size_t)k * WKN + c8 * 8),
                   Wsrc + (size_t)k * 128 + c8 * 8);
    }
}

#define ZACC(acc, MF, NF)                             \
    _Pragma("unroll") for (int mf = 0; mf < MF; ++mf) \
    _Pragma("unroll") for (int nf = 0; nf < NF; ++nf) \
    _Pragma("unroll") for (int j = 0; j < 4; ++j) acc[mf][nf][j] = 0.f;

__device__ __forceinline__ void write_c_h(
    __half* __restrict__ C, const float* __restrict__ bias,
    int row0, int wrow, int wcol, int gid, int tig,
    float acc[2][4][4], int M)
{
#pragma unroll
    for (int nf = 0; nf < 4; ++nf) {
        const int c = wcol + nf * 8 + tig * 2;
        const float b0 = bias[c], b1 = bias[c + 1];
#pragma unroll
        for (int mf = 0; mf < 2; ++mf)
#pragma unroll
            for (int h = 0; h < 2; ++h) {
                const int r = row0 + wrow + mf * 16 + h * 8 + gid;
                if (r < M)
                    *(__half2*)(C + (size_t)r * 128 + c) =
                        __floats2half2_rn(acc[mf][nf][2 * h] + b0, acc[mf][nf][2 * h + 1] + b1);
            }
    }
}

// ---------- weight fp32 -> fp16 converter ----------
__global__ void f2h_kernel(const float* __restrict__ src, __half* __restrict__ dst, int n4)
{
    int i = blockIdx.x * 256 + threadIdx.x;
    if (i < n4) {
        float4 v = ((const float4*)src)[i];
        __half2 a = __floats2half2_rn(v.x, v.y);
        __half2 b = __floats2half2_rn(v.z, v.w);
        *(uint2*)(dst + (size_t)i * 4) = make_uint2(*(uint32_t*)&a, *(uint32_t*)&b);
    }
}

// ---------- fused embed + dual transform (BM=64, 3 CTAs/SM) + acc/den zeroing ----------
__global__ __launch_bounds__(256, 3) void embed_dual(
    const float* __restrict__ x, const float* __restrict__ be,
    const __half* __restrict__ WhE, const __half* __restrict__ WhL,
    const __half* __restrict__ WhR,
    const float* __restrict__ bl, const float* __restrict__ br,
    __half* __restrict__ Hout, __half* __restrict__ Cl, __half* __restrict__ Cr,
    __half* __restrict__ Accz, float* __restrict__ Denz, int M)
{
    extern __shared__ __half shh[];
    __half* AsH = shh;                    // 64 x APD (phase A uses pitch APE)
    __half* Wb0 = shh + 64 * APD;
    __half* Wb1 = Wb0 + 64 * WKN;
    const int tid = threadIdx.x;
    const int row0 = blockIdx.x * 64;

    // prefetch We chunk (overlaps x staging + acc zeroing)
    stage_w_async(WhE, Wb0, tid);
    CP_COMMIT();

    // zero this block's slice of acc (fp16) and den
    {
        const uint4 z = make_uint4(0u, 0u, 0u, 0u);
        int nrow = min(64, M - row0);
        for (int i = tid; i < nrow * 16; i += 256)
            ((uint4*)Accz)[(size_t)row0 * 16 + i] = z;
        if (tid < nrow) Denz[row0 + tid] = 0.f;
    }
    // stage x (fp16, pitch APE)
    for (int i = tid; i < 64 * 16; i += 256) {
        int r = i >> 4, c4 = i & 15;
        int gr = row0 + r;
        float4 v = make_float4(0.f, 0.f, 0.f, 0.f);
        if (gr < M) v = ((const float4*)(x + (size_t)gr * 64))[c4];
        __half2 h01 = __floats2half2_rn(v.x, v.y);
        __half2 h23 = __floats2half2_rn(v.z, v.w);
        *(uint2*)(AsH + (size_t)r * APE + c4 * 4) =
            make_uint2(*(uint32_t*)&h01, *(uint32_t*)&h23);
    }
    CP_WAIT0();
    __syncthreads();

    const int wid = tid >> 5, lane = tid & 31;
    const int wm = wid & 1, wn = wid >> 1;          // 2x4 warp grid, tile 32x32
    const int wrow = wm * 32, wcol = wn * 32;
    const int gid = lane >> 2, tig = lane & 3;

    float acc[2][4][4];
    ZACC(acc, 2, 4)
    mma_chunk64h<2, 4>(AsH, APE, 0, Wb0, wrow, wcol, lane, acc);

    // prefetch phase-B chunk0 (Wl rows 0..63) into Wb1
    stage_w_async(WhL, Wb1, tid);
    CP_COMMIT();
    __syncthreads();   // phase-A AsH/Wb0 reads complete before overwrite

    // epilogue h: write gmem fp16 + restage fp16 into AsH (pitch APD)
#pragma unroll
    for (int nf = 0; nf < 4; ++nf) {
        const int c = wcol + nf * 8 + tig * 2;
        const float b0 = be[c], b1 = be[c + 1];
#pragma unroll
        for (int mf = 0; mf < 2; ++mf)
#pragma unroll
            for (int h = 0; h < 2; ++h) {
                const int rl = wrow + mf * 16 + h * 8 + gid;
                const float v0 = acc[mf][nf][2 * h] + b0;
                const float v1 = acc[mf][nf][2 * h + 1] + b1;
                const int gr = row0 + rl;
                __half2 hv = __floats2half2_rn(v0, v1);
                if (gr < M)
                    *(__half2*)(Hout + (size_t)gr * 128 + c) = hv;
                *(__half2*)(AsH + (size_t)rl * APD + c) = hv;
            }
    }
    CP_WAIT0();
    __syncthreads();   // Wb1 ready + AsH writes visible

    // phase B: 4 chunks {Wl0@Wb1, Wl1@Wb0, Wr0@Wb1, Wr1@Wb0}
    const __half* seq1 = WhL + 64 * 128;
    const __half* seq2 = WhR;
    const __half* seq3 = WhR + 64 * 128;
    __half* bufs[2] = {Wb0, Wb1};

    ZACC(acc, 2, 4)
    // c=0
    stage_w_async(seq1, Wb0, tid); CP_COMMIT();
    mma_chunk64h<2, 4>(AsH, APD, 0, Wb1, wrow, wcol, lane, acc);
    CP_WAIT0(); __syncthreads();
    // c=1
    stage_w_async(seq2, Wb1, tid); CP_COMMIT();
    mma_chunk64h<2, 4>(AsH, APD, 64, Wb0, wrow, wcol, lane, acc);
    write_c_h(Cl, bl, row0, wrow, wcol, gid, tig, acc, M);
    CP_WAIT0(); __syncthreads();
    // c=2
    ZACC(acc, 2, 4)
    stage_w_async(seq3, Wb0, tid); CP_COMMIT();
    mma_chunk64h<2, 4>(AsH, APD, 0, Wb1, wrow, wcol, lane, acc);
    CP_WAIT0(); __syncthreads();
    // c=3
    mma_chunk64h<2, 4>(AsH, APD, 64, Wb0, wrow, wcol, lane, acc);
    write_c_h(Cr, br, row0, wrow, wcol, gid, tig, acc, M);
    (void)bufs;
}

// ---------- dual transform with fused update + zero-after-read (BM=64, 3 CTAs/SM) ----------
__global__ __launch_bounds__(256, 3) void dual_upd(
    __half* __restrict__ H, __half* __restrict__ Acc, float* __restrict__ Den,
    const float* __restrict__ ubias,
    const __half* __restrict__ WhL, const __half* __restrict__ WhR,
    const float* __restrict__ bl, const float* __restrict__ br,
    __half* __restrict__ Cl, __half* __restrict__ Cr, int M)
{
    extern __shared__ __half shh[];
    __half* AsH = shh;                    // 64 x APD
    __half* Wb0 = shh + 64 * APD;
    __half* Wb1 = Wb0 + 64 * WKN;
    const int tid = threadIdx.x;
    const int row0 = blockIdx.x * 64;

    // prefetch chunk0 (Wl rows 0..63) — overlaps A staging
    stage_w_async(WhL, Wb0, tid);
    CP_COMMIT();

    // stage A with fused update: h1 = h + relu(acc/den + ubias)
    for (int i = tid; i < 64 * 32; i += 256) {
        int r = i >> 5, c4 = i & 31;
        int gr = row0 + r;
        float4 hv = make_float4(0.f, 0.f, 0.f, 0.f);
        if (gr < M) {
            float inv = 1.f / (Den[gr] + 1e-16f);
            const __half2* ah = (const __half2*)Acc + (size_t)gr * 64 + c4 * 2;
            float2 a01 = __half22float2(ah[0]);
            float2 a23 = __half22float2(ah[1]);
            const __half2* hh = (const __half2*)H + (size_t)gr * 64 + c4 * 2;
            float2 h01 = __half22float2(hh[0]);
            float2 h23 = __half22float2(hh[1]);
            const float4 bb = ((const float4*)ubias)[c4];
            hv.x = h01.x + fmaxf(a01.x * inv + bb.x, 0.f);
            hv.y = h01.y + fmaxf(a01.y * inv + bb.y, 0.f);
            hv.z = h23.x + fmaxf(a23.x * inv + bb.z, 0.f);
            hv.w = h23.y + fmaxf(a23.y * inv + bb.w, 0.f);
            __half2 o01 = __floats2half2_rn(hv.x, hv.y);
            __half2 o23 = __floats2half2_rn(hv.z, hv.w);
            *(uint2*)((__half2*)H + (size_t)gr * 64 + c4 * 2) =
                make_uint2(*(uint32_t*)&o01, *(uint32_t*)&o23);
        }
        __half2 h01 = __floats2half2_rn(hv.x, hv.y);
        __half2 h23 = __floats2half2_rn(hv.z, hv.w);
        *(uint2*)(AsH + (size_t)r * APD + c4 * 4) =
            make_uint2(*(uint32_t*)&h01, *(uint32_t*)&h23);
    }
    CP_WAIT0();
    __syncthreads();   // acc/den reads complete + AsH + Wb0 ready

    // zero-after-read: re-zero acc/den for the next edge pass (background stores)
    {
        const uint4 z = make_uint4(0u, 0u, 0u, 0u);
        int nrow = min(64, M - row0);
        for (int i = tid; i < nrow * 16; i += 256)
            ((uint4*)Acc)[(size_t)row0 * 16 + i] = z;
        if (tid < nrow) Den[row0 + tid] = 0.f;
    }

    const int wid = tid >> 5, lane = tid & 31;
    const int wm = wid & 1, wn = wid >> 1;
    const int wrow = wm * 32, wcol = wn * 32;
    const int gid = lane >> 2, tig = lane & 3;

    float acc[2][4][4];
    ZACC(acc, 2, 4)
    // chunks {Wl0@Wb0, Wl1@Wb1, Wr0@Wb0, Wr1@Wb1}
    // c=0
    stage_w_async(WhL + 64 * 128, Wb1, tid); CP_COMMIT();
    mma_chunk64h<2, 4>(AsH, APD, 0, Wb0, wrow, wcol, lane, acc);
    CP_WAIT0(); __syncthreads();
    // c=1
    stage_w_async(WhR, Wb0, tid); CP_COMMIT();
    mma_chunk64h<2, 4>(AsH, APD, 64, Wb1, wrow, wcol, lane, acc);
    write_c_h(Cl, bl, row0, wrow, wcol, gid, tig, acc, M);
    CP_WAIT0(); __syncthreads();
    // c=2
    ZACC(acc, 2, 4)
    stage_w_async(WhR + 64 * 128, Wb1, tid); CP_COMMIT();
    mma_chunk64h<2, 4>(AsH, APD, 0, Wb0, wrow, wcol, lane, acc);
    CP_WAIT0(); __syncthreads();
    // c=3
    mma_chunk64h<2, 4>(AsH, APD, 64, Wb1, wrow, wcol, lane, acc);
    write_c_h(Cr, br, row0, wrow, wcol, gid, tig, acc, M);
}

// ---------- fused edge pass: warp per edge, fp16 xl/xr/acc ----------
__global__ void edge_kernel(const int* __restrict__ src, const int* __restrict__ dst,
                            const float* __restrict__ att)
{
    int e = (int)(((size_t)blockIdx.x * blockDim.x + threadIdx.x) >> 5);
    if (e >= NE) return;
    int ln = threadIdx.x & 31;
    int s = src[e], d = dst[e];
    const __half2* xap = (const __half2*)g_xl + (size_t)s * 64 + ln * 2;
    const __half2* xbp = (const __half2*)g_xr + (size_t)d * 64 + ln * 2;
    __half2 xa2[2], xb2[2];
    *(uint2*)xa2 = *(const uint2*)xap;
    *(uint2*)xb2 = *(const uint2*)xbp;
    float2 xa01 = __half22float2(xa2[0]);
    float2 xa23 = __half22float2(xa2[1]);
    float2 xb01 = __half22float2(xb2[0]);
    float2 xb23 = __half22float2(xb2[1]);
    float4 at = ((const float4*)att)[ln];

    float vx = xa01.x + xb01.x; vx = vx > 0.f ? vx : 0.2f * vx;
    float vy = xa01.y + xb01.y; vy = vy > 0.f ? vy : 0.2f * vy;
    float vz = xa23.x + xb23.x; vz = vz > 0.f ? vz : 0.2f * vz;
    float vw = xa23.y + xb23.y; vw = vw > 0.f ? vw : 0.2f * vw;
    float p = vx * at.x + vy * at.y + vz * at.z + vw * at.w;
#pragma unroll
    for (int o = 16; o > 0; o >>= 1) p += __shfl_xor_sync(0xffffffffu, p, o);
    float e_ = __expf(p);
    if (ln == 0) atomicAdd(&g_den[d], e_);
    __half2* accd = (__half2*)g_acc + (size_t)d * 64 + ln * 2;
    atomicAdd(accd + 0, __floats2half2_rn(e_ * xa01.x, e_ * xa01.y));
    atomicAdd(accd + 1, __floats2half2_rn(e_ * xa23.x, e_ * xa23.y));
}

// ---------- mega head: BM=64, warp tile 32x32 grid 2x4, 2 CTAs/SM ----------
__global__ __launch_bounds__(256, 2) void head_kernel(
    const __half* __restrict__ H, const __half* __restrict__ Acc, const float* __restrict__ Den,
    const float* __restrict__ ubias,
    const int* __restrict__ child, const int* __restrict__ parent,
    const float* __restrict__ ttab, const int* __restrict__ timei,
    const __half* __restrict__ WhComb, const float* __restrict__ b_comb,
    const __half* __restrict__ WhA1, const float* __restrict__ cadd,
    const float* __restrict__ W_a2, const float* __restrict__ b_a2,
    float* __restrict__ out, int M)
{
    extern __shared__ __half shh[];
    __half* AsH = shh;                       // 64 x APHD
    __half* Wb0 = shh + 64 * APHD;
    __half* Wb1 = Wb0 + 64 * WKN;
    float*  red = (float*)(Wb1 + 64 * WKN);  // 4 x 64
    const int tid = threadIdx.x;
    const int row0 = blockIdx.x * 64;

    // prefetch Wcomb chunk0 — overlaps gather staging
    stage_w_async(WhComb, Wb0, tid);
    CP_COMMIT();

    // stage cat(h2[child], h2[parent]|0), h2 = h1 + relu(acc/den + ubias)
    for (int i = tid; i < 64 * 64; i += 256) {
        int r = i >> 6, c4 = i & 63;
        int gr = row0 + r;
        float4 v = make_float4(0.f, 0.f, 0.f, 0.f);
        if (gr < M) {
            int cc = c4 < 32 ? c4 : c4 - 32;
            int ri = c4 < 32 ? child[gr] : parent[gr];
            if (ri >= 0) {
                float inv = 1.f / (Den[ri] + 1e-16f);
                const __half2* ah = (const __half2*)Acc + (size_t)ri * 64 + cc * 2;
                float2 a01 = __half22float2(ah[0]);
                float2 a23 = __half22float2(ah[1]);
                const __half2* hh = (const __half2*)H + (size_t)ri * 64 + cc * 2;
                float2 h01 = __half22float2(hh[0]);
                float2 h23 = __half22float2(hh[1]);
                float4 bb = ((const float4*)ubias)[cc];
                v.x = h01.x + fmaxf(a01.x * inv + bb.x, 0.f);
                v.y = h01.y + fmaxf(a01.y * inv + bb.y, 0.f);
                v.z = h23.x + fmaxf(a23.x * inv + bb.z, 0.f);
                v.w = h23.y + fmaxf(a23.y * inv + bb.w, 0.f);
            }
        }
        __half2 h01 = __floats2half2_rn(v.x, v.y);
        __half2 h23 = __floats2half2_rn(v.z, v.w);
        *(uint2*)(AsH + (size_t)r * APHD + c4 * 4) =
            make_uint2(*(uint32_t*)&h01, *(uint32_t*)&h23);
    }
    CP_WAIT0();
    __syncthreads();

    const int wid = tid >> 5, lane = tid & 31;
    const int wm = wid & 1, wn = wid >> 1;
    const int wrow = wm * 32, wcol = wn * 32;
    const int gid = lane >> 2, tig = lane & 3;

    float acc[2][4][4];
    ZACC(acc, 2, 4)

    // GEMM1: 4 chunks {C0@Wb0, C1@Wb1, C2@Wb0, C3@Wb1}
    stage_w_async(WhComb + 1 * 64 * 128, Wb1, tid); CP_COMMIT();
    mma_chunk64h<2, 4>(AsH, APHD, 0, Wb0, wrow, wcol, lane, acc);
    CP_WAIT0(); __syncthreads();
    stage_w_async(WhComb + 2 * 64 * 128, Wb0, tid); CP_COMMIT();
    mma_chunk64h<2, 4>(AsH, APHD, 64, Wb1, wrow, wcol, lane, acc);
    CP_WAIT0(); __syncthreads();
    stage_w_async(WhComb + 3 * 64 * 128, Wb1, tid); CP_COMMIT();
    mma_chunk64h<2, 4>(AsH, APHD, 128, Wb0, wrow, wcol, lane, acc);
    CP_WAIT0(); __syncthreads();
    stage_w_async(WhA1, Wb0, tid); CP_COMMIT();   // prefetch GEMM2 chunk0 over epilogue
    mma_chunk64h<2, 4>(AsH, APHD, 192, Wb1, wrow, wcol, lane, acc);
    __syncthreads();   // GEMM1 AsH reads complete before overwrite

    // epilogue1: branch(+b_comb) -> AsH cols [0,128)
#pragma unroll
    for (int nf = 0; nf < 4; ++nf) {
        const int c = wcol + nf * 8 + tig * 2;
        const float b0 = b_comb[c], b1 = b_comb[c + 1];
#pragma unroll
        for (int mf = 0; mf < 2; ++mf)
#pragma unroll
            for (int h = 0; h < 2; ++h) {
                const int rl = wrow + mf * 16 + h * 8 + gid;
                *(__half2*)(AsH + (size_t)rl * APHD + c) =
                    __floats2half2_rn(acc[mf][nf][2 * h] + b0, acc[mf][nf][2 * h + 1] + b1);
            }
    }
    // stage t_emb -> AsH cols [128,256)
    for (int i = tid; i < 64 * 32; i += 256) {
        int r = i >> 5, c4 = i & 31;
        int gr = row0 + r;
        float4 v = make_float4(0.f, 0.f, 0.f, 0.f);
        if (gr < M) {
            int t = timei[gr];
            v = ((const float4*)(ttab + (size_t)t * 128))[c4];
        }
        __half2 h01 = __floats2half2_rn(v.x, v.y);
        __half2 h23 = __floats2half2_rn(v.z, v.w);
        *(uint2*)(AsH + (size_t)r * APHD + 128 + c4 * 4) =
            make_uint2(*(uint32_t*)&h01, *(uint32_t*)&h23);
    }
    CP_WAIT0();
    __syncthreads();

    // GEMM2: 4 chunks {A0@Wb0, A1@Wb1, A2@Wb0, A3@Wb1}
    ZACC(acc, 2, 4)
    stage_w_async(WhA1 + 1 * 64 * 128, Wb1, tid); CP_COMMIT();
    mma_chunk64h<2, 4>(AsH, APHD, 0, Wb0, wrow, wcol, lane, acc);
    CP_WAIT0(); __syncthreads();
    stage_w_async(WhA1 + 2 * 64 * 128, Wb0, tid); CP_COMMIT();
    mma_chunk64h<2, 4>(AsH, APHD, 64, Wb1, wrow, wcol, lane, acc);
    CP_WAIT0(); __syncthreads();
    stage_w_async(WhA1 + 3 * 64 * 128, Wb1, tid); CP_COMMIT();
    mma_chunk64h<2, 4>(AsH, APHD, 128, Wb0, wrow, wcol, lane, acc);
    CP_WAIT0(); __syncthreads();
    mma_chunk64h<2, 4>(AsH, APHD, 192, Wb1, wrow, wcol, lane, acc);

    // epilogue2: dot with W_a2
    float p[2][2] = {{0.f, 0.f}, {0.f, 0.f}};
#pragma unroll
    for (int nf = 0; nf < 4; ++nf) {
        const int c = wcol + nf * 8 + tig * 2;
        const float ca0 = cadd[c], ca1 = cadd[c + 1];
        const float w20 = W_a2[c], w21 = W_a2[c + 1];
#pragma unroll
        for (int mf = 0; mf < 2; ++mf)
#pragma unroll
            for (int h = 0; h < 2; ++h) {
                float v0 = fmaxf(acc[mf][nf][2 * h]     + ca0, 0.f);
                float v1 = fmaxf(acc[mf][nf][2 * h + 1] + ca1, 0.f);
                p[mf][h] += v0 * w20 + v1 * w21;
            }
    }
#pragma unroll
    for (int o = 1; o <= 2; o <<= 1)
#pragma unroll
        for (int mf = 0; mf < 2; ++mf)
#pragma unroll
            for (int h = 0; h < 2; ++h)
                p[mf][h] += __shfl_xor_sync(0xffffffffu, p[mf][h], o);

    __syncthreads();
    if (tig == 0) {
#pragma unroll
        for (int mf = 0; mf < 2; ++mf)
#pragma unroll
            for (int h = 0; h < 2; ++h)
                red[wn * 64 + wrow + mf * 16 + h * 8 + gid] = p[mf][h];
    }
    __syncthreads();
    if (tid < 64) {
        int gr = row0 + tid;
        if (gr < M)
            out[gr] = red[tid] + red[64 + tid] + red[128 + tid] + red[192 + tid] + b_a2[0];
    }
}

// ---------------- fused context precompute ----------------
__global__ void ctx_cadd_kernel(const float* __restrict__ focal, const float* __restrict__ W_seq,
                                const float* __restrict__ b_seq,
                                const float* __restrict__ W_a1, const float* __restrict__ b_a1)
{
    __shared__ float cs[128];
    int j = threadIdx.x;
    float s = b_seq[j];
    for (int d = 0; d < DD; ++d) s += focal[d] * W_seq[d * 128 + j];
    cs[j] = s;
    __syncthreads();
    float t = b_a1[j];
    for (int k = 0; k < 128; ++k) t += cs[k] * W_a1[(256 + k) * 128 + j];
    g_cadd[j] = t;
}

// ---------------- launch ----------------
extern "C" void kernel_launch(void* const* d_in, const int* in_sizes, int n_in,
                              void* d_out, int out_size)
{
    const float* x       = (const float*)d_in[0];
    const int*   ei      = (const int*)  d_in[1];
    const float* focal   = (const float*)d_in[2];
    const int*   child   = (const int*)  d_in[3];
    const int*   parent  = (const int*)  d_in[4];
    const int*   timei   = (const int*)  d_in[5];
    const float* W_embed = (const float*)d_in[6];
    const float* b_embed = (const float*)d_in[7];
    const float* bu_Wl   = (const float*)d_in[8];
    const float* bu_bl   = (const float*)d_in[9];
    const float* bu_Wr   = (const float*)d_in[10];
    const float* bu_br   = (const float*)d_in[11];
    const float* bu_att  = (const float*)d_in[12];
    const float* bu_bias = (const float*)d_in[13];
    const float* td_Wl   = (const float*)d_in[14];
    const float* td_bl   = (const float*)d_in[15];
    const float* td_Wr   = (const float*)d_in[16];
    const float* td_br   = (const float*)d_in[17];
    const float* td_att  = (const float*)d_in[18];
    const float* td_bias = (const float*)d_in[19];
    const float* ttab    = (const float*)d_in[20];
    const float* W_comb  = (const float*)d_in[21];
    const float* b_comb  = (const float*)d_in[22];
    const float* W_a1    = (const float*)d_in[23];
    const float* b_a1    = (const float*)d_in[24];
    const float* W_a2    = (const float*)d_in[25];
    const float* b_a2    = (const float*)d_in[26];
    const float* W_seq   = (const float*)d_in[27];
    const float* b_seq   = (const float*)d_in[28];
    float* out = (float*)d_out;

    const int SM_DUAL = (64 * APD + 2 * 64 * WKN) * 2;            // 52,224 B (3 CTAs/SM)
    const int SM_HEAD = (64 * APHD + 2 * 64 * WKN) * 2 + 256 * 4; // 69,632 B (2 CTAs/SM)
    cudaFuncSetAttribute(embed_dual,  cudaFuncAttributeMaxDynamicSharedMemorySize, SM_DUAL);
    cudaFuncSetAttribute(dual_upd,    cudaFuncAttributeMaxDynamicSharedMemorySize, SM_DUAL);
    cudaFuncSetAttribute(head_kernel, cudaFuncAttributeMaxDynamicSharedMemorySize, SM_HEAD);

    float *denp, *caddp;
    __half *hp, *xlp, *xrp, *accp, *whp;
    cudaGetSymbolAddress((void**)&hp,    g_h);
    cudaGetSymbolAddress((void**)&xlp,   g_xl);
    cudaGetSymbolAddress((void**)&xrp,   g_xr);
    cudaGetSymbolAddress((void**)&accp,  g_acc);
    cudaGetSymbolAddress((void**)&denp,  g_den);
    cudaGetSymbolAddress((void**)&caddp, g_cadd);
    cudaGetSymbolAddress((void**)&whp,   g_wh);

    const int GEMM_BLKS_N = (NN + 63) / 64;
    const int HEAD_BLKS   = (NA + 63) / 64;
    const int EDGE_BLKS   = (NE + 7) / 8;

    // -1) convert weights to fp16 (dense [k][128])
    f2h_kernel<<<(2048 + 255) / 256, 256>>>(W_embed, whp + OFF_WE,    2048);
    f2h_kernel<<<(4096 + 255) / 256, 256>>>(bu_Wl,   whp + OFF_BUWL,  4096);
    f2h_kernel<<<(4096 + 255) / 256, 256>>>(bu_Wr,   whp + OFF_BUWR,  4096);
    f2h_kernel<<<(4096 + 255) / 256, 256>>>(td_Wl,   whp + OFF_TDWL,  4096);
    f2h_kernel<<<(4096 + 255) / 256, 256>>>(td_Wr,   whp + OFF_TDWR,  4096);
    f2h_kernel<<<(8192 + 255) / 256, 256>>>(W_comb,  whp + OFF_WCOMB, 8192);
    f2h_kernel<<<(8192 + 255) / 256, 256>>>(W_a1,    whp + OFF_WA1,   8192);

    // 0) context fold
    ctx_cadd_kernel<<<1, 128>>>(focal, W_seq, b_seq, W_a1, b_a1);

    // 1) embed + bottom-up transforms + acc/den zeroing (src = row1, dst = row0)
    embed_dual<<<GEMM_BLKS_N, 256, SM_DUAL>>>(x, b_embed,
                                              whp + OFF_WE, whp + OFF_BUWL, whp + OFF_BUWR,
                                              bu_bl, bu_br,
                                              hp, xlp, xrp, accp, denp, NN);
    edge_kernel<<<EDGE_BLKS, 256>>>(ei + NE, ei, bu_att);

    // 2) update1 fused + top-down transforms + zero-after-read (src = row0, dst = row1)
    dual_upd<<<GEMM_BLKS_N, 256, SM_DUAL>>>(hp, accp, denp, bu_bias,
                                            whp + OFF_TDWL, whp + OFF_TDWR,
                                            td_bl, td_br, xlp, xrp, NN);
    edge_kernel<<<EDGE_BLKS, 256>>>(ei, ei + NE, td_att);

    // 3) head with on-the-fly update2
    head_kernel<<<HEAD_BLKS, 256, SM_HEAD>>>(hp, accp, denp, td_bias,
                                             child, parent, ttab, timei,
                                             whp + OFF_WCOMB, b_comb,
                                             whp + OFF_WA1, caddp,
                                             W_a2, b_a2, out, NA);
}